// round 1
// baseline (speedup 1.0000x reference)
#include <cuda_runtime.h>
#include <cstddef>

#define BB 4
#define SS 2048
#define DD 1024
#define HH 16
#define AA 64

// Scratch for per-head projections, layout [B,H,S,A]
__device__ float g_qh[BB*HH*SS*AA];
__device__ float g_kh[BB*HH*SS*AA];
__device__ float g_vh[BB*HH*SS*AA];

// ---------------------------------------------------------------------------
// Stage 1: per-head projection GEMM
// Out[b,h,s,a] = sum_d X[b,s,d] * W[h,d,a] + bias[h,a]
// grid (M/128=64, H=16), 256 threads, micro-tile 8x4, BK=32
// ---------------------------------------------------------------------------
__global__ __launch_bounds__(256) void proj_kernel(
    const float* __restrict__ X, const float* __restrict__ W,
    const float* __restrict__ bias, int which)
{
    float* Out = (which == 0) ? g_qh : (which == 1) ? g_kh : g_vh;

    __shared__ float Xs[128][36];  // natural layout, padded (stores: conflict-free STS.128)
    __shared__ float Ws[32][64];

    const int t  = threadIdx.x;
    const int tx = t & 15, ty = t >> 4;
    const int m0 = blockIdx.x * 128;
    const int h  = blockIdx.y;

    const float* Wh = W + (size_t)h * DD * AA;

    float acc[8][4];
#pragma unroll
    for (int i = 0; i < 8; i++)
#pragma unroll
        for (int j = 0; j < 4; j++) acc[i][j] = 0.f;

    for (int k0 = 0; k0 < DD; k0 += 32) {
        __syncthreads();
        // load X tile 128x32
#pragma unroll
        for (int p = 0; p < 4; p++) {
            int idx = t + 256 * p;
            int r  = idx >> 3;          // 0..127
            int c4 = (idx & 7) * 4;     // 0..28
            float4 v = *(const float4*)(X + (size_t)(m0 + r) * DD + k0 + c4);
            *(float4*)(&Xs[r][c4]) = v;
        }
        // load W tile 32x64
#pragma unroll
        for (int p = 0; p < 2; p++) {
            int idx = t + 256 * p;
            int d  = idx >> 4;
            int v4 = (idx & 15) * 4;
            *(float4*)(&Ws[d][v4]) = *(const float4*)(Wh + (size_t)(k0 + d) * AA + v4);
        }
        __syncthreads();
#pragma unroll 8
        for (int d = 0; d < 32; d++) {
            float4 wf = *(const float4*)(&Ws[d][tx * 4]);
#pragma unroll
            for (int i = 0; i < 8; i++) {
                float x = Xs[ty * 8 + i][d];   // broadcast over tx
                acc[i][0] += x * wf.x;
                acc[i][1] += x * wf.y;
                acc[i][2] += x * wf.z;
                acc[i][3] += x * wf.w;
            }
        }
    }

    float4 bv = *(const float4*)(bias + h * AA + tx * 4);
    const int b      = m0 / SS;   // 128 | 2048 so whole block in one b
    const int s_base = m0 % SS;
#pragma unroll
    for (int i = 0; i < 8; i++) {
        int s = s_base + ty * 8 + i;
        float4 r;
        r.x = acc[i][0] + bv.x;
        r.y = acc[i][1] + bv.y;
        r.z = acc[i][2] + bv.z;
        r.w = acc[i][3] + bv.w;
        *(float4*)(Out + ((size_t)(b * HH + h) * SS + s) * AA + tx * 4) = r;
    }
}

// ---------------------------------------------------------------------------
// Stage 2: flash-attention (no scale, no mask), fp32 online softmax
// grid (S/128=16, H=16, B=4), 256 threads.
// Tiles: Q 128x64, K 128x64, V 128x64, P 128x128.
// S-compute micro 8q x 8k (k = j*16+tx, pitch 65 -> conflict-free LDS)
// PV micro 8q x 4a (Vs pitch 68 -> conflict-free LDS.128)
// ---------------------------------------------------------------------------
#define QS_PITCH 65
#define KS_PITCH 65
#define PS_PITCH 130
#define VS_PITCH 68

__global__ __launch_bounds__(256) void attn_kernel(float* __restrict__ out)
{
    extern __shared__ float sm[];
    float* Qs = sm;                                   // [128][65]
    float* Ks = sm + 128 * QS_PITCH;                  // [128][65]
    float* Ps = sm + 2 * 128 * QS_PITCH;              // [128][130]
    float* Vs = sm + 2 * 128 * QS_PITCH + 128 * PS_PITCH; // [128][68]

    const int t  = threadIdx.x;
    const int tx = t & 15, ty = t >> 4;
    const int qt = blockIdx.x, h = blockIdx.y, b = blockIdx.z;

    const float* qb  = g_qh + ((size_t)(b * HH + h) * SS + qt * 128) * AA;
    const float* kb0 = g_kh + (size_t)(b * HH + h) * SS * AA;
    const float* vb0 = g_vh + (size_t)(b * HH + h) * SS * AA;

    // load Q tile
#pragma unroll
    for (int p = 0; p < 8; p++) {
        int idx = t + 256 * p;
        int r = idx >> 4, c = (idx & 15) * 4;
        float4 v = *(const float4*)(qb + (size_t)r * AA + c);
        Qs[r * QS_PITCH + c]     = v.x;
        Qs[r * QS_PITCH + c + 1] = v.y;
        Qs[r * QS_PITCH + c + 2] = v.z;
        Qs[r * QS_PITCH + c + 3] = v.w;
    }

    float m[8], l[8], o[8][4];
#pragma unroll
    for (int i = 0; i < 8; i++) {
        m[i] = -1e30f;
        l[i] = 0.f;
#pragma unroll
        for (int j = 0; j < 4; j++) o[i][j] = 0.f;
    }

    for (int kt = 0; kt < SS / 128; kt++) {
        __syncthreads();
        const float* kb = kb0 + (size_t)kt * 128 * AA;
        const float* vb = vb0 + (size_t)kt * 128 * AA;
#pragma unroll
        for (int p = 0; p < 8; p++) {
            int idx = t + 256 * p;
            int r = idx >> 4, c = (idx & 15) * 4;
            float4 kv = *(const float4*)(kb + (size_t)r * AA + c);
            Ks[r * KS_PITCH + c]     = kv.x;
            Ks[r * KS_PITCH + c + 1] = kv.y;
            Ks[r * KS_PITCH + c + 2] = kv.z;
            Ks[r * KS_PITCH + c + 3] = kv.w;
            *(float4*)(Vs + r * VS_PITCH + c) = *(const float4*)(vb + (size_t)r * AA + c);
        }
        __syncthreads();

        // S = Q K^T  (8x8 per thread; q = ty*8+i, k = j*16+tx)
        float sc[8][8];
#pragma unroll
        for (int i = 0; i < 8; i++)
#pragma unroll
            for (int j = 0; j < 8; j++) sc[i][j] = 0.f;

#pragma unroll 4
        for (int d = 0; d < 64; d++) {
            float qf[8], kf[8];
#pragma unroll
            for (int i = 0; i < 8; i++) qf[i] = Qs[(ty * 8 + i) * QS_PITCH + d];
#pragma unroll
            for (int j = 0; j < 8; j++) kf[j] = Ks[(j * 16 + tx) * KS_PITCH + d];
#pragma unroll
            for (int i = 0; i < 8; i++)
#pragma unroll
                for (int j = 0; j < 8; j++) sc[i][j] += qf[i] * kf[j];
        }

        // online softmax update + write P
#pragma unroll
        for (int i = 0; i < 8; i++) {
            float mx = sc[i][0];
#pragma unroll
            for (int j = 1; j < 8; j++) mx = fmaxf(mx, sc[i][j]);
#pragma unroll
            for (int off = 1; off < 16; off <<= 1)
                mx = fmaxf(mx, __shfl_xor_sync(0xffffffffu, mx, off));
            float mn   = fmaxf(m[i], mx);
            float corr = __expf(m[i] - mn);
            float rs = 0.f;
#pragma unroll
            for (int j = 0; j < 8; j++) {
                float p = __expf(sc[i][j] - mn);
                sc[i][j] = p;
                rs += p;
            }
#pragma unroll
            for (int off = 1; off < 16; off <<= 1)
                rs += __shfl_xor_sync(0xffffffffu, rs, off);
            m[i] = mn;
            l[i] = l[i] * corr + rs;
            o[i][0] *= corr; o[i][1] *= corr; o[i][2] *= corr; o[i][3] *= corr;
#pragma unroll
            for (int j = 0; j < 8; j++)
                Ps[(ty * 8 + i) * PS_PITCH + j * 16 + tx] = sc[i][j];
        }
        __syncthreads();

        // O += P V   (8q x 4a per thread)
#pragma unroll 2
        for (int k = 0; k < 128; k++) {
            float4 vv = *(const float4*)(Vs + k * VS_PITCH + tx * 4);
#pragma unroll
            for (int i = 0; i < 8; i++) {
                float p = Ps[(ty * 8 + i) * PS_PITCH + k];
                o[i][0] += p * vv.x;
                o[i][1] += p * vv.y;
                o[i][2] += p * vv.z;
                o[i][3] += p * vv.w;
            }
        }
    }

    // epilogue: normalize, write [B,S,H*A]
#pragma unroll
    for (int i = 0; i < 8; i++) {
        float inv = 1.f / l[i];
        int q = qt * 128 + ty * 8 + i;
        float4 r;
        r.x = o[i][0] * inv;
        r.y = o[i][1] * inv;
        r.z = o[i][2] * inv;
        r.w = o[i][3] * inv;
        *(float4*)(out + ((size_t)(b * SS + q) * HH + h) * AA + tx * 4) = r;
    }
}

// ---------------------------------------------------------------------------

static const size_t ATTN_SMEM =
    (size_t)(2 * 128 * QS_PITCH + 128 * PS_PITCH + 128 * VS_PITCH) * sizeof(float); // 167936 B

extern "C" void kernel_launch(void* const* d_in, const int* in_sizes, int n_in,
                              void* d_out, int out_size)
{
    const float* q  = (const float*)d_in[0];
    const float* k  = (const float*)d_in[1];
    const float* v  = (const float*)d_in[2];
    const float* Wq = (const float*)d_in[3];
    const float* bq = (const float*)d_in[4];
    const float* Wk = (const float*)d_in[5];
    const float* bk = (const float*)d_in[6];
    const float* Wv = (const float*)d_in[7];
    const float* bv = (const float*)d_in[8];
    float* out = (float*)d_out;

    cudaFuncSetAttribute(attn_kernel, cudaFuncAttributeMaxDynamicSharedMemorySize,
                         (int)ATTN_SMEM);

    dim3 pgrid(64, 16);
    proj_kernel<<<pgrid, 256>>>(q, Wq, bq, 0);
    proj_kernel<<<pgrid, 256>>>(k, Wk, bk, 1);
    proj_kernel<<<pgrid, 256>>>(v, Wv, bv, 2);

    dim3 agrid(16, 16, 4);
    attn_kernel<<<agrid, 256, ATTN_SMEM>>>(out);
}

// round 3
// speedup vs baseline: 1.7434x; 1.7434x over previous
#include <cuda_runtime.h>
#include <cuda_bf16.h>
#include <cstdint>
#include <cstddef>

#define BB 4
#define SS 2048
#define DD 1024
#define HH 16
#define AA 64

// Split bf16 (hi/lo) projections, layout [B,H,S,A]
__device__ __nv_bfloat16 g_qhh[BB*HH*SS*AA];
__device__ __nv_bfloat16 g_qhl[BB*HH*SS*AA];
__device__ __nv_bfloat16 g_khh[BB*HH*SS*AA];
__device__ __nv_bfloat16 g_khl[BB*HH*SS*AA];
__device__ __nv_bfloat16 g_vhh[BB*HH*SS*AA];
__device__ __nv_bfloat16 g_vhl[BB*HH*SS*AA];

// ---------------------------------------------------------------------------
// helpers
// ---------------------------------------------------------------------------
__device__ __forceinline__ uint32_t smem_u32(const void* p) {
    uint32_t a;
    asm("{ .reg .u64 t; cvta.to.shared.u64 t, %1; cvt.u32.u64 %0, t; }" : "=r"(a) : "l"(p));
    return a;
}

__device__ __forceinline__ void mma16816(float* d, uint32_t a0, uint32_t a1,
                                         uint32_t a2, uint32_t a3,
                                         uint32_t b0, uint32_t b1) {
    asm volatile(
        "mma.sync.aligned.m16n8k16.row.col.f32.bf16.bf16.f32 "
        "{%0,%1,%2,%3}, {%4,%5,%6,%7}, {%8,%9}, {%0,%1,%2,%3};"
        : "+f"(d[0]), "+f"(d[1]), "+f"(d[2]), "+f"(d[3])
        : "r"(a0), "r"(a1), "r"(a2), "r"(a3), "r"(b0), "r"(b1));
}

__device__ __forceinline__ void ldsm4(uint32_t& r0, uint32_t& r1, uint32_t& r2,
                                      uint32_t& r3, uint32_t addr) {
    asm volatile("ldmatrix.sync.aligned.m8n8.x4.shared.b16 {%0,%1,%2,%3}, [%4];"
        : "=r"(r0), "=r"(r1), "=r"(r2), "=r"(r3) : "r"(addr));
}
__device__ __forceinline__ void ldsm4t(uint32_t& r0, uint32_t& r1, uint32_t& r2,
                                       uint32_t& r3, uint32_t addr) {
    asm volatile("ldmatrix.sync.aligned.m8n8.x4.trans.shared.b16 {%0,%1,%2,%3}, [%4];"
        : "=r"(r0), "=r"(r1), "=r"(r2), "=r"(r3) : "r"(addr));
}

// pack two floats -> bf16x2 (x0 in low half), plus bf16x2 of the residuals
__device__ __forceinline__ void split_pack(float x0, float x1, uint32_t& h, uint32_t& l) {
    uint32_t hh;
    asm("cvt.rn.bf16x2.f32 %0, %1, %2;" : "=r"(hh) : "f"(x1), "f"(x0));
    float f0 = __uint_as_float(hh << 16);
    float f1 = __uint_as_float(hh & 0xffff0000u);
    float r0 = x0 - f0, r1 = x1 - f1;
    asm("cvt.rn.bf16x2.f32 %0, %1, %2;" : "=r"(l) : "f"(r1), "f"(r0));
    h = hh;
}

__device__ __forceinline__ void split_bf(float x, __nv_bfloat16& hi, __nv_bfloat16& lo) {
    hi = __float2bfloat16(x);
    lo = __float2bfloat16(x - __bfloat162float(hi));
}

// ---------------------------------------------------------------------------
// Stage 1: per-head projection GEMM (fp32 FFMA), epilogue emits bf16 hi/lo
// ---------------------------------------------------------------------------
__global__ __launch_bounds__(256) void proj_kernel(
    const float* __restrict__ X, const float* __restrict__ W,
    const float* __restrict__ bias, int which)
{
    __nv_bfloat16* Ohi = (which == 0) ? g_qhh : (which == 1) ? g_khh : g_vhh;
    __nv_bfloat16* Olo = (which == 0) ? g_qhl : (which == 1) ? g_khl : g_vhl;

    __shared__ float Xs[128][36];
    __shared__ float Ws[32][64];

    const int t  = threadIdx.x;
    const int tx = t & 15, ty = t >> 4;
    const int m0 = blockIdx.x * 128;
    const int h  = blockIdx.y;
    const float* Wh = W + (size_t)h * DD * AA;

    float acc[8][4];
#pragma unroll
    for (int i = 0; i < 8; i++)
#pragma unroll
        for (int j = 0; j < 4; j++) acc[i][j] = 0.f;

    for (int k0 = 0; k0 < DD; k0 += 32) {
        __syncthreads();
#pragma unroll
        for (int p = 0; p < 4; p++) {
            int idx = t + 256 * p;
            int r = idx >> 3, c4 = (idx & 7) * 4;
            *(float4*)(&Xs[r][c4]) = *(const float4*)(X + (size_t)(m0 + r) * DD + k0 + c4);
        }
#pragma unroll
        for (int p = 0; p < 2; p++) {
            int idx = t + 256 * p;
            int d = idx >> 4, v4 = (idx & 15) * 4;
            *(float4*)(&Ws[d][v4]) = *(const float4*)(Wh + (size_t)(k0 + d) * AA + v4);
        }
        __syncthreads();
#pragma unroll 8
        for (int d = 0; d < 32; d++) {
            float4 wf = *(const float4*)(&Ws[d][tx * 4]);
#pragma unroll
            for (int i = 0; i < 8; i++) {
                float x = Xs[ty * 8 + i][d];
                acc[i][0] += x * wf.x; acc[i][1] += x * wf.y;
                acc[i][2] += x * wf.z; acc[i][3] += x * wf.w;
            }
        }
    }

    float4 bv = *(const float4*)(bias + h * AA + tx * 4);
    const int b = m0 / SS;
    const int s_base = m0 % SS;
#pragma unroll
    for (int i = 0; i < 8; i++) {
        int s = s_base + ty * 8 + i;
        float r0 = acc[i][0] + bv.x, r1 = acc[i][1] + bv.y;
        float r2 = acc[i][2] + bv.z, r3 = acc[i][3] + bv.w;
        __nv_bfloat16 h0,h1,h2,h3,l0,l1,l2,l3;
        split_bf(r0,h0,l0); split_bf(r1,h1,l1); split_bf(r2,h2,l2); split_bf(r3,h3,l3);
        size_t off = ((size_t)(b * HH + h) * SS + s) * AA + tx * 4;
        __nv_bfloat162 hA(h0,h1), hB(h2,h3), lA(l0,l1), lB(l2,l3);
        uint2 uh, ul;
        uh.x = *(uint32_t*)&hA; uh.y = *(uint32_t*)&hB;
        ul.x = *(uint32_t*)&lA; ul.y = *(uint32_t*)&lB;
        *(uint2*)(Ohi + off) = uh;
        *(uint2*)(Olo + off) = ul;
    }
}

// ---------------------------------------------------------------------------
// Stage 2: mma.sync bf16 flash attention with hi/lo split, fixed shift C
// 256 threads = 8 warps; warp w owns q-rows [16w,16w+16) of a 128-row tile.
// K processed in chunks of 64 keys (32 iterations).
// ---------------------------------------------------------------------------
#define PITCH 144   // bytes per smem row (72 halves): conflict-free ldmatrix

static constexpr int SQH = 0;
static constexpr int SQL = SQH + 128 * PITCH;   // 18432
static constexpr int SKH = SQL + 128 * PITCH;   // 36864
static constexpr int SKL = SKH + 64 * PITCH;    // 46080
static constexpr int SVH = SKL + 64 * PITCH;    // 55296
static constexpr int SVL = SVH + 64 * PITCH;    // 64512
static constexpr int SM_TOTAL = SVL + 64 * PITCH; // 73728

// load a 64x64 bf16 tile (rows of 128B) into pitch-144 smem
__device__ __forceinline__ void load64(const __nv_bfloat16* g, char* s, int t) {
#pragma unroll
    for (int j = 0; j < 2; j++) {
        int idx = t + 256 * j;
        int r = idx >> 3, c = (idx & 7) * 8;
        *(uint4*)(s + r * PITCH + c * 2) = *(const uint4*)(g + (size_t)r * AA + c);
    }
}

__global__ __launch_bounds__(256, 2) void attn_mma(float* __restrict__ out)
{
    extern __shared__ char smc[];
    const uint32_t sb = smem_u32(smc);
    const int t = threadIdx.x, lane = t & 31, w = t >> 5;
    const int qt = blockIdx.x, h = blockIdx.y, b = blockIdx.z;
    const size_t bh = (size_t)(b * HH + h) * SS;

    // load Q tiles (128x64 hi/lo)
    {
        const __nv_bfloat16* qh = g_qhh + (bh + qt * 128) * AA;
        const __nv_bfloat16* ql = g_qhl + (bh + qt * 128) * AA;
#pragma unroll
        for (int j = 0; j < 4; j++) {
            int idx = t + 256 * j;
            int r = idx >> 3, c = (idx & 7) * 8;
            *(uint4*)(smc + SQH + r * PITCH + c * 2) = *(const uint4*)(qh + (size_t)r * AA + c);
            *(uint4*)(smc + SQL + r * PITCH + c * 2) = *(const uint4*)(ql + (size_t)r * AA + c);
        }
    }

    // ldmatrix lane address components
    const int lr  = lane & 7;
    const int grp = lane >> 3;
    // A (non-trans, 16x16): rows lr + (grp&1)*8, colbytes (grp>>1)*16
    const uint32_t a_row = 16 * w + lr + (grp & 1) * 8;
    const uint32_t a_cb  = (grp >> 1) * 16;
    // B for K (non-trans): rows lr + (grp>>1)*8, colbytes (grp&1)*16
    const uint32_t kb_row = lr + (grp >> 1) * 8;
    const uint32_t kb_cb  = (grp & 1) * 16;
    // B for V (trans): rows lr + (grp&1)*8, colbytes (grp>>1)*16
    const uint32_t vb_row = lr + (grp & 1) * 8;
    const uint32_t vb_cb  = (grp >> 1) * 16;

    const uint32_t aqh = sb + SQH + a_row * PITCH + a_cb;
    const uint32_t aql = sb + SQL + a_row * PITCH + a_cb;

    float oacc[8][4];
#pragma unroll
    for (int i = 0; i < 8; i++)
#pragma unroll
        for (int j = 0; j < 4; j++) oacc[i][j] = 0.f;
    float lA = 0.f, lB = 0.f, CA = 0.f, CB = 0.f;

    for (int kt = 0; kt < SS / 64; kt++) {
        __syncthreads();
        const size_t ko = (bh + kt * 64) * AA;
        load64(g_khh + ko, smc + SKH, t);
        load64(g_khl + ko, smc + SKL, t);
        load64(g_vhh + ko, smc + SVH, t);
        load64(g_vhl + ko, smc + SVL, t);
        __syncthreads();

        // ---- S = Q K^T : 8 n-tiles (16 rows x 64 cols per warp) ----
        float sacc[8][4];
#pragma unroll
        for (int i = 0; i < 8; i++)
#pragma unroll
            for (int j = 0; j < 4; j++) sacc[i][j] = 0.f;

#pragma unroll
        for (int ks = 0; ks < 4; ks++) {      // a-dim steps of 16
            uint32_t qh0, qh1, qh2, qh3, ql0, ql1, ql2, ql3;
            ldsm4(qh0, qh1, qh2, qh3, aqh + ks * 32);
            ldsm4(ql0, ql1, ql2, ql3, aql + ks * 32);
#pragma unroll
            for (int np = 0; np < 4; np++) {  // 16 k-rows per pair
                uint32_t kh0, kh1, kh2, kh3, kl0, kl1, kl2, kl3;
                uint32_t kaddr = sb + (np * 16 + kb_row) * PITCH + ks * 32 + kb_cb;
                ldsm4(kh0, kh1, kh2, kh3, SKH + kaddr);
                ldsm4(kl0, kl1, kl2, kl3, SKL + kaddr);
                mma16816(sacc[2*np],   qh0, qh1, qh2, qh3, kh0, kh1);
                mma16816(sacc[2*np+1], qh0, qh1, qh2, qh3, kh2, kh3);
                mma16816(sacc[2*np],   qh0, qh1, qh2, qh3, kl0, kl1);
                mma16816(sacc[2*np+1], qh0, qh1, qh2, qh3, kl2, kl3);
                mma16816(sacc[2*np],   ql0, ql1, ql2, ql3, kh0, kh1);
                mma16816(sacc[2*np+1], ql0, ql1, ql2, ql3, kh2, kh3);
            }
        }

        // ---- softmax (fixed shift from first chunk) ----
        if (kt == 0) {
            float mA = -1e30f, mB = -1e30f;
#pragma unroll
            for (int i = 0; i < 8; i++) {
                mA = fmaxf(mA, fmaxf(sacc[i][0], sacc[i][1]));
                mB = fmaxf(mB, fmaxf(sacc[i][2], sacc[i][3]));
            }
            mA = fmaxf(mA, __shfl_xor_sync(0xffffffffu, mA, 1));
            mA = fmaxf(mA, __shfl_xor_sync(0xffffffffu, mA, 2));
            mB = fmaxf(mB, __shfl_xor_sync(0xffffffffu, mB, 1));
            mB = fmaxf(mB, __shfl_xor_sync(0xffffffffu, mB, 2));
            CA = mA; CB = mB;
        }
#pragma unroll
        for (int i = 0; i < 8; i++) {
            sacc[i][0] = __expf(sacc[i][0] - CA);
            sacc[i][1] = __expf(sacc[i][1] - CA);
            sacc[i][2] = __expf(sacc[i][2] - CB);
            sacc[i][3] = __expf(sacc[i][3] - CB);
            lA += sacc[i][0] + sacc[i][1];
            lB += sacc[i][2] + sacc[i][3];
        }

        // ---- O += P V ----
#pragma unroll
        for (int ks = 0; ks < 4; ks++) {      // k-dim steps of 16
            uint32_t ph0, ph1, ph2, ph3, pl0, pl1, pl2, pl3;
            split_pack(sacc[2*ks][0],   sacc[2*ks][1],   ph0, pl0);
            split_pack(sacc[2*ks][2],   sacc[2*ks][3],   ph1, pl1);
            split_pack(sacc[2*ks+1][0], sacc[2*ks+1][1], ph2, pl2);
            split_pack(sacc[2*ks+1][2], sacc[2*ks+1][3], ph3, pl3);
#pragma unroll
            for (int np = 0; np < 4; np++) {  // 16 a-cols per pair
                uint32_t vh0, vh1, vh2, vh3, vl0, vl1, vl2, vl3;
                uint32_t vaddr = sb + (ks * 16 + vb_row) * PITCH + np * 32 + vb_cb;
                ldsm4t(vh0, vh1, vh2, vh3, SVH + vaddr);
                ldsm4t(vl0, vl1, vl2, vl3, SVL + vaddr);
                mma16816(oacc[2*np],   ph0, ph1, ph2, ph3, vh0, vh1);
                mma16816(oacc[2*np+1], ph0, ph1, ph2, ph3, vh2, vh3);
                mma16816(oacc[2*np],   ph0, ph1, ph2, ph3, vl0, vl1);
                mma16816(oacc[2*np+1], ph0, ph1, ph2, ph3, vl2, vl3);
                mma16816(oacc[2*np],   pl0, pl1, pl2, pl3, vh0, vh1);
                mma16816(oacc[2*np+1], pl0, pl1, pl2, pl3, vh2, vh3);
            }
        }
    }

    // ---- epilogue: normalize + write out[b, s, h*64+a] ----
    lA += __shfl_xor_sync(0xffffffffu, lA, 1);
    lA += __shfl_xor_sync(0xffffffffu, lA, 2);
    lB += __shfl_xor_sync(0xffffffffu, lB, 1);
    lB += __shfl_xor_sync(0xffffffffu, lB, 2);
    float invA = 1.f / lA, invB = 1.f / lB;

    int rA = qt * 128 + 16 * w + (lane >> 2);
    int col = 2 * (lane & 3);
    float* oA = out + ((size_t)(b * SS + rA)) * (HH * AA) + h * AA + col;
    float* oB = oA + 8 * (HH * AA);
#pragma unroll
    for (int j = 0; j < 8; j++) {
        float2 vA = make_float2(oacc[j][0] * invA, oacc[j][1] * invA);
        float2 vB = make_float2(oacc[j][2] * invB, oacc[j][3] * invB);
        *(float2*)(oA + j * 8) = vA;
        *(float2*)(oB + j * 8) = vB;
    }
}

// ---------------------------------------------------------------------------

extern "C" void kernel_launch(void* const* d_in, const int* in_sizes, int n_in,
                              void* d_out, int out_size)
{
    const float* q  = (const float*)d_in[0];
    const float* k  = (const float*)d_in[1];
    const float* v  = (const float*)d_in[2];
    const float* Wq = (const float*)d_in[3];
    const float* bq = (const float*)d_in[4];
    const float* Wk = (const float*)d_in[5];
    const float* bk = (const float*)d_in[6];
    const float* Wv = (const float*)d_in[7];
    const float* bv = (const float*)d_in[8];
    float* out = (float*)d_out;

    cudaFuncSetAttribute(attn_mma, cudaFuncAttributeMaxDynamicSharedMemorySize, SM_TOTAL);

    dim3 pgrid(64, 16);
    proj_kernel<<<pgrid, 256>>>(q, Wq, bq, 0);
    proj_kernel<<<pgrid, 256>>>(k, Wk, bk, 1);
    proj_kernel<<<pgrid, 256>>>(v, Wv, bv, 2);

    dim3 agrid(16, 16, 4);
    attn_mma<<<agrid, 256, SM_TOTAL>>>(out);
}

// round 4
// speedup vs baseline: 2.8097x; 1.6116x over previous
#include <cuda_runtime.h>
#include <cuda_bf16.h>
#include <cstdint>
#include <cstddef>

#define BB 4
#define SS 2048
#define DD 1024
#define HH 16
#define AA 64

#define NX (BB*SS*DD)     // 8388608 elems per input tensor
#define NW (HH*DD*AA)     // 1048576 elems per weight tensor
#define NP (BB*HH*SS*AA)  // 8388608 elems per projection output

// bf16 hi/lo splits: inputs, weights, projection outputs ([B,H,S,A])
__device__ __nv_bfloat16 g_xh[3][NX], g_xl[3][NX];
__device__ __nv_bfloat16 g_wh[3][NW], g_wl[3][NW];
__device__ __nv_bfloat16 g_ph[3][NP], g_pl[3][NP];

// ---------------------------------------------------------------------------
// helpers
// ---------------------------------------------------------------------------
__device__ __forceinline__ uint32_t smem_u32(const void* p) {
    uint32_t a;
    asm("{ .reg .u64 t; cvta.to.shared.u64 t, %1; cvt.u32.u64 %0, t; }" : "=r"(a) : "l"(p));
    return a;
}

__device__ __forceinline__ void mma16816(float* d, uint32_t a0, uint32_t a1,
                                         uint32_t a2, uint32_t a3,
                                         uint32_t b0, uint32_t b1) {
    asm volatile(
        "mma.sync.aligned.m16n8k16.row.col.f32.bf16.bf16.f32 "
        "{%0,%1,%2,%3}, {%4,%5,%6,%7}, {%8,%9}, {%0,%1,%2,%3};"
        : "+f"(d[0]), "+f"(d[1]), "+f"(d[2]), "+f"(d[3])
        : "r"(a0), "r"(a1), "r"(a2), "r"(a3), "r"(b0), "r"(b1));
}

__device__ __forceinline__ void ldsm4(uint32_t& r0, uint32_t& r1, uint32_t& r2,
                                      uint32_t& r3, uint32_t addr) {
    asm volatile("ldmatrix.sync.aligned.m8n8.x4.shared.b16 {%0,%1,%2,%3}, [%4];"
        : "=r"(r0), "=r"(r1), "=r"(r2), "=r"(r3) : "r"(addr));
}
__device__ __forceinline__ void ldsm4t(uint32_t& r0, uint32_t& r1, uint32_t& r2,
                                       uint32_t& r3, uint32_t addr) {
    asm volatile("ldmatrix.sync.aligned.m8n8.x4.trans.shared.b16 {%0,%1,%2,%3}, [%4];"
        : "=r"(r0), "=r"(r1), "=r"(r2), "=r"(r3) : "r"(addr));
}

// pack two floats -> bf16x2 (x0 in low half), plus bf16x2 of the residuals
__device__ __forceinline__ void split_pack(float x0, float x1, uint32_t& h, uint32_t& l) {
    uint32_t hh;
    asm("cvt.rn.bf16x2.f32 %0, %1, %2;" : "=r"(hh) : "f"(x1), "f"(x0));
    float f0 = __uint_as_float(hh << 16);
    float f1 = __uint_as_float(hh & 0xffff0000u);
    float r0 = x0 - f0, r1 = x1 - f1;
    asm("cvt.rn.bf16x2.f32 %0, %1, %2;" : "=r"(l) : "f"(r1), "f"(r0));
    h = hh;
}

// ---------------------------------------------------------------------------
// Stage 0: split fp32 tensors into bf16 hi/lo
// kind=0 -> g_xh/g_xl[which] (NX elems); kind=1 -> g_wh/g_wl[which] (NW elems)
// ---------------------------------------------------------------------------
__global__ __launch_bounds__(256) void conv_split(const float* __restrict__ in,
                                                  int which, int kind, int n4)
{
    __nv_bfloat16* hi = kind ? g_wh[which] : g_xh[which];
    __nv_bfloat16* lo = kind ? g_wl[which] : g_xl[which];
    int idx = blockIdx.x * 256 + threadIdx.x;
    if (idx >= n4) return;
    float4 v = ((const float4*)in)[idx];
    uint32_t h0, l0, h1, l1;
    split_pack(v.x, v.y, h0, l0);
    split_pack(v.z, v.w, h1, l1);
    ((uint2*)hi)[idx] = make_uint2(h0, h1);
    ((uint2*)lo)[idx] = make_uint2(l0, l1);
}

// ---------------------------------------------------------------------------
// Stage 1: projection GEMM on tensor cores (split bf16)
// Out[b,h,s,a] = X[b,s,:] @ W[h,:,a] + bias[h,a]
// CTA: 128 rows x 2 heads (N=128). 8 warps, warp w: rows [16w,16w+16) x 128 cols
// grid (H/2=8, M/128=64): head-pair fastest -> X slices reused in L2
// ---------------------------------------------------------------------------
#define PX 144   // X smem pitch (bytes): 64 halves + pad, conflict-free ldmatrix
#define PW 272   // W smem pitch (bytes): 128 halves + pad

static constexpr int SXH = 0;
static constexpr int SXL = SXH + 128 * PX;   // 18432
static constexpr int SWH = SXL + 128 * PX;   // 36864
static constexpr int SWL = SWH + 64 * PW;    // 54272
static constexpr int PROJ_SMEM = SWL + 64 * PW; // 71680

__global__ __launch_bounds__(256, 2) void proj_mma(int which, const float* __restrict__ bias)
{
    extern __shared__ char smc[];
    const uint32_t sb = smem_u32(smc);
    const int t = threadIdx.x, lane = t & 31, w = t >> 5;
    const int h0 = blockIdx.x * 2;
    const int m0 = blockIdx.y * 128;

    const __nv_bfloat16* Xh = g_xh[which];
    const __nv_bfloat16* Xl = g_xl[which];
    const __nv_bfloat16* Wh_ = g_wh[which];
    const __nv_bfloat16* Wl_ = g_wl[which];
    __nv_bfloat16* Oh = g_ph[which];
    __nv_bfloat16* Ol = g_pl[which];

    const int lr  = lane & 7;
    const int grp = lane >> 3;
    // A (X, non-trans 16x16)
    const uint32_t a_row = 16 * w + lr + (grp & 1) * 8;
    const uint32_t a_cb  = (grp >> 1) * 16;
    // B (W, trans: [k][n] row-major like V)
    const uint32_t wb_row = lr + (grp & 1) * 8;
    const uint32_t wb_cb  = (grp >> 1) * 16;

    const uint32_t axh = sb + SXH + a_row * PX + a_cb;
    const uint32_t axl = sb + SXL + a_row * PX + a_cb;

    float acc[16][4];
#pragma unroll
    for (int i = 0; i < 16; i++)
#pragma unroll
        for (int j = 0; j < 4; j++) acc[i][j] = 0.f;

    for (int k0 = 0; k0 < DD; k0 += 64) {
        __syncthreads();
        // X tile: 128 rows x 64 cols (hi+lo)
#pragma unroll
        for (int j = 0; j < 4; j++) {
            int idx = t + 256 * j;
            int r = idx >> 3, c8 = (idx & 7) * 8;
            size_t go = (size_t)(m0 + r) * DD + k0 + c8;
            *(uint4*)(smc + SXH + r * PX + c8 * 2) = *(const uint4*)(Xh + go);
            *(uint4*)(smc + SXL + r * PX + c8 * 2) = *(const uint4*)(Xl + go);
        }
        // W tile: 64 k-rows x 128 n-cols (2 heads) (hi+lo)
#pragma unroll
        for (int j = 0; j < 4; j++) {
            int idx = t + 256 * j;
            int r = idx >> 4, c16 = (idx & 15) * 8;
            int hh_ = h0 + (c16 >> 6), a = c16 & 63;
            size_t go = ((size_t)hh_ * DD + (k0 + r)) * AA + a;
            *(uint4*)(smc + SWH + r * PW + c16 * 2) = *(const uint4*)(Wh_ + go);
            *(uint4*)(smc + SWL + r * PW + c16 * 2) = *(const uint4*)(Wl_ + go);
        }
        __syncthreads();

#pragma unroll
        for (int ks = 0; ks < 4; ks++) {
            uint32_t xh0, xh1, xh2, xh3, xl0, xl1, xl2, xl3;
            ldsm4(xh0, xh1, xh2, xh3, axh + ks * 32);
            ldsm4(xl0, xl1, xl2, xl3, axl + ks * 32);
#pragma unroll
            for (int np = 0; np < 8; np++) {
                uint32_t wh0, wh1, wh2, wh3, wl0, wl1, wl2, wl3;
                uint32_t waddr = sb + (ks * 16 + wb_row) * PW + np * 32 + wb_cb;
                ldsm4t(wh0, wh1, wh2, wh3, SWH + waddr);
                ldsm4t(wl0, wl1, wl2, wl3, SWL + waddr);
                mma16816(acc[2*np],   xh0, xh1, xh2, xh3, wh0, wh1);
                mma16816(acc[2*np+1], xh0, xh1, xh2, xh3, wh2, wh3);
                mma16816(acc[2*np],   xh0, xh1, xh2, xh3, wl0, wl1);
                mma16816(acc[2*np+1], xh0, xh1, xh2, xh3, wl2, wl3);
                mma16816(acc[2*np],   xl0, xl1, xl2, xl3, wh0, wh1);
                mma16816(acc[2*np+1], xl0, xl1, xl2, xl3, wh2, wh3);
            }
        }
    }

    // epilogue: +bias, split to bf16 hi/lo, store [B,H,S,A]
    const int bidx = m0 / SS;
    const int srow = m0 % SS;
    const int rlo = lane >> 2;
    const int cp  = 2 * (lane & 3);
#pragma unroll
    for (int j = 0; j < 16; j++) {
        int n = 8 * j + cp;
        int hh_ = h0 + (n >> 6);
        int a = n & 63;
        float b0 = bias[hh_ * AA + a], b1 = bias[hh_ * AA + a + 1];
        int s0 = srow + 16 * w + rlo;
        size_t o0 = ((size_t)(bidx * HH + hh_) * SS + s0) * AA + a;
        size_t o1 = o0 + (size_t)8 * AA;
        uint32_t hv, lv;
        split_pack(acc[j][0] + b0, acc[j][1] + b1, hv, lv);
        *(uint32_t*)(Oh + o0) = hv; *(uint32_t*)(Ol + o0) = lv;
        split_pack(acc[j][2] + b0, acc[j][3] + b1, hv, lv);
        *(uint32_t*)(Oh + o1) = hv; *(uint32_t*)(Ol + o1) = lv;
    }
}

// ---------------------------------------------------------------------------
// Stage 2: mma.sync bf16 flash attention with hi/lo split, fixed shift C
// (unchanged from R3 except pointer names)
// ---------------------------------------------------------------------------
#define PITCH 144

static constexpr int SQH = 0;
static constexpr int SQL = SQH + 128 * PITCH;
static constexpr int SKH = SQL + 128 * PITCH;
static constexpr int SKL = SKH + 64 * PITCH;
static constexpr int SVH = SKL + 64 * PITCH;
static constexpr int SVL = SVH + 64 * PITCH;
static constexpr int SM_TOTAL = SVL + 64 * PITCH; // 73728

__device__ __forceinline__ void load64(const __nv_bfloat16* g, char* s, int t) {
#pragma unroll
    for (int j = 0; j < 2; j++) {
        int idx = t + 256 * j;
        int r = idx >> 3, c = (idx & 7) * 8;
        *(uint4*)(s + r * PITCH + c * 2) = *(const uint4*)(g + (size_t)r * AA + c);
    }
}

__global__ __launch_bounds__(256, 2) void attn_mma(float* __restrict__ out)
{
    extern __shared__ char smc[];
    const uint32_t sb = smem_u32(smc);
    const int t = threadIdx.x, lane = t & 31, w = t >> 5;
    const int qt = blockIdx.x, h = blockIdx.y, b = blockIdx.z;
    const size_t bh = (size_t)(b * HH + h) * SS;

    {
        const __nv_bfloat16* qh = g_ph[0] + (bh + qt * 128) * AA;
        const __nv_bfloat16* ql = g_pl[0] + (bh + qt * 128) * AA;
#pragma unroll
        for (int j = 0; j < 4; j++) {
            int idx = t + 256 * j;
            int r = idx >> 3, c = (idx & 7) * 8;
            *(uint4*)(smc + SQH + r * PITCH + c * 2) = *(const uint4*)(qh + (size_t)r * AA + c);
            *(uint4*)(smc + SQL + r * PITCH + c * 2) = *(const uint4*)(ql + (size_t)r * AA + c);
        }
    }

    const int lr  = lane & 7;
    const int grp = lane >> 3;
    const uint32_t a_row = 16 * w + lr + (grp & 1) * 8;
    const uint32_t a_cb  = (grp >> 1) * 16;
    const uint32_t kb_row = lr + (grp >> 1) * 8;
    const uint32_t kb_cb  = (grp & 1) * 16;
    const uint32_t vb_row = lr + (grp & 1) * 8;
    const uint32_t vb_cb  = (grp >> 1) * 16;

    const uint32_t aqh = sb + SQH + a_row * PITCH + a_cb;
    const uint32_t aql = sb + SQL + a_row * PITCH + a_cb;

    float oacc[8][4];
#pragma unroll
    for (int i = 0; i < 8; i++)
#pragma unroll
        for (int j = 0; j < 4; j++) oacc[i][j] = 0.f;
    float lA = 0.f, lB = 0.f, CA = 0.f, CB = 0.f;

    for (int kt = 0; kt < SS / 64; kt++) {
        __syncthreads();
        const size_t ko = (bh + kt * 64) * AA;
        load64(g_ph[1] + ko, smc + SKH, t);
        load64(g_pl[1] + ko, smc + SKL, t);
        load64(g_ph[2] + ko, smc + SVH, t);
        load64(g_pl[2] + ko, smc + SVL, t);
        __syncthreads();

        float sacc[8][4];
#pragma unroll
        for (int i = 0; i < 8; i++)
#pragma unroll
            for (int j = 0; j < 4; j++) sacc[i][j] = 0.f;

#pragma unroll
        for (int ks = 0; ks < 4; ks++) {
            uint32_t qh0, qh1, qh2, qh3, ql0, ql1, ql2, ql3;
            ldsm4(qh0, qh1, qh2, qh3, aqh + ks * 32);
            ldsm4(ql0, ql1, ql2, ql3, aql + ks * 32);
#pragma unroll
            for (int np = 0; np < 4; np++) {
                uint32_t kh0, kh1, kh2, kh3, kl0, kl1, kl2, kl3;
                uint32_t kaddr = sb + (np * 16 + kb_row) * PITCH + ks * 32 + kb_cb;
                ldsm4(kh0, kh1, kh2, kh3, SKH + kaddr);
                ldsm4(kl0, kl1, kl2, kl3, SKL + kaddr);
                mma16816(sacc[2*np],   qh0, qh1, qh2, qh3, kh0, kh1);
                mma16816(sacc[2*np+1], qh0, qh1, qh2, qh3, kh2, kh3);
                mma16816(sacc[2*np],   qh0, qh1, qh2, qh3, kl0, kl1);
                mma16816(sacc[2*np+1], qh0, qh1, qh2, qh3, kl2, kl3);
                mma16816(sacc[2*np],   ql0, ql1, ql2, ql3, kh0, kh1);
                mma16816(sacc[2*np+1], ql0, ql1, ql2, ql3, kh2, kh3);
            }
        }

        if (kt == 0) {
            float mA = -1e30f, mB = -1e30f;
#pragma unroll
            for (int i = 0; i < 8; i++) {
                mA = fmaxf(mA, fmaxf(sacc[i][0], sacc[i][1]));
                mB = fmaxf(mB, fmaxf(sacc[i][2], sacc[i][3]));
            }
            mA = fmaxf(mA, __shfl_xor_sync(0xffffffffu, mA, 1));
            mA = fmaxf(mA, __shfl_xor_sync(0xffffffffu, mA, 2));
            mB = fmaxf(mB, __shfl_xor_sync(0xffffffffu, mB, 1));
            mB = fmaxf(mB, __shfl_xor_sync(0xffffffffu, mB, 2));
            CA = mA; CB = mB;
        }
#pragma unroll
        for (int i = 0; i < 8; i++) {
            sacc[i][0] = __expf(sacc[i][0] - CA);
            sacc[i][1] = __expf(sacc[i][1] - CA);
            sacc[i][2] = __expf(sacc[i][2] - CB);
            sacc[i][3] = __expf(sacc[i][3] - CB);
            lA += sacc[i][0] + sacc[i][1];
            lB += sacc[i][2] + sacc[i][3];
        }

#pragma unroll
        for (int ks = 0; ks < 4; ks++) {
            uint32_t ph0, ph1, ph2, ph3, pl0, pl1, pl2, pl3;
            split_pack(sacc[2*ks][0],   sacc[2*ks][1],   ph0, pl0);
            split_pack(sacc[2*ks][2],   sacc[2*ks][3],   ph1, pl1);
            split_pack(sacc[2*ks+1][0], sacc[2*ks+1][1], ph2, pl2);
            split_pack(sacc[2*ks+1][2], sacc[2*ks+1][3], ph3, pl3);
#pragma unroll
            for (int np = 0; np < 4; np++) {
                uint32_t vh0, vh1, vh2, vh3, vl0, vl1, vl2, vl3;
                uint32_t vaddr = sb + (ks * 16 + vb_row) * PITCH + np * 32 + vb_cb;
                ldsm4t(vh0, vh1, vh2, vh3, SVH + vaddr);
                ldsm4t(vl0, vl1, vl2, vl3, SVL + vaddr);
                mma16816(oacc[2*np],   ph0, ph1, ph2, ph3, vh0, vh1);
                mma16816(oacc[2*np+1], ph0, ph1, ph2, ph3, vh2, vh3);
                mma16816(oacc[2*np],   ph0, ph1, ph2, ph3, vl0, vl1);
                mma16816(oacc[2*np+1], ph0, ph1, ph2, ph3, vl2, vl3);
                mma16816(oacc[2*np],   pl0, pl1, pl2, pl3, vh0, vh1);
                mma16816(oacc[2*np+1], pl0, pl1, pl2, pl3, vh2, vh3);
            }
        }
    }

    lA += __shfl_xor_sync(0xffffffffu, lA, 1);
    lA += __shfl_xor_sync(0xffffffffu, lA, 2);
    lB += __shfl_xor_sync(0xffffffffu, lB, 1);
    lB += __shfl_xor_sync(0xffffffffu, lB, 2);
    float invA = 1.f / lA, invB = 1.f / lB;

    int rA = qt * 128 + 16 * w + (lane >> 2);
    int col = 2 * (lane & 3);
    float* oA = out + ((size_t)(b * SS + rA)) * (HH * AA) + h * AA + col;
    float* oB = oA + 8 * (HH * AA);
#pragma unroll
    for (int j = 0; j < 8; j++) {
        float2 vA = make_float2(oacc[j][0] * invA, oacc[j][1] * invA);
        float2 vB = make_float2(oacc[j][2] * invB, oacc[j][3] * invB);
        *(float2*)(oA + j * 8) = vA;
        *(float2*)(oB + j * 8) = vB;
    }
}

// ---------------------------------------------------------------------------

extern "C" void kernel_launch(void* const* d_in, const int* in_sizes, int n_in,
                              void* d_out, int out_size)
{
    const float* q  = (const float*)d_in[0];
    const float* k  = (const float*)d_in[1];
    const float* v  = (const float*)d_in[2];
    const float* Wq = (const float*)d_in[3];
    const float* bq = (const float*)d_in[4];
    const float* Wk = (const float*)d_in[5];
    const float* bk = (const float*)d_in[6];
    const float* Wv = (const float*)d_in[7];
    const float* bv = (const float*)d_in[8];
    float* out = (float*)d_out;

    cudaFuncSetAttribute(proj_mma, cudaFuncAttributeMaxDynamicSharedMemorySize, PROJ_SMEM);
    cudaFuncSetAttribute(attn_mma, cudaFuncAttributeMaxDynamicSharedMemorySize, SM_TOTAL);

    // stage 0: splits
    conv_split<<<NX/4/256, 256>>>(q, 0, 0, NX/4);
    conv_split<<<NX/4/256, 256>>>(k, 1, 0, NX/4);
    conv_split<<<NX/4/256, 256>>>(v, 2, 0, NX/4);
    conv_split<<<NW/4/256, 256>>>(Wq, 0, 1, NW/4);
    conv_split<<<NW/4/256, 256>>>(Wk, 1, 1, NW/4);
    conv_split<<<NW/4/256, 256>>>(Wv, 2, 1, NW/4);

    // stage 1: projections
    dim3 pgrid(HH/2, 64);
    proj_mma<<<pgrid, 256, PROJ_SMEM>>>(0, bq);
    proj_mma<<<pgrid, 256, PROJ_SMEM>>>(1, bk);
    proj_mma<<<pgrid, 256, PROJ_SMEM>>>(2, bv);

    // stage 2: attention
    dim3 agrid(16, 16, 4);
    attn_mma<<<agrid, 256, SM_TOTAL>>>(out);
}

// round 5
// speedup vs baseline: 3.0240x; 1.0763x over previous
#include <cuda_runtime.h>
#include <cuda_bf16.h>
#include <cstdint>
#include <cstddef>

#define BB 4
#define SS 2048
#define DD 1024
#define HH 16
#define AA 64

#define NX (BB*SS*DD)
#define NW (HH*DD*AA)
#define NP (BB*HH*SS*AA)

__device__ __nv_bfloat16 g_xh[3][NX], g_xl[3][NX];
__device__ __nv_bfloat16 g_wh[3][NW], g_wl[3][NW];
__device__ __nv_bfloat16 g_ph[3][NP], g_pl[3][NP];

// ---------------------------------------------------------------------------
__device__ __forceinline__ uint32_t smem_u32(const void* p) {
    uint32_t a;
    asm("{ .reg .u64 t; cvta.to.shared.u64 t, %1; cvt.u32.u64 %0, t; }" : "=r"(a) : "l"(p));
    return a;
}
__device__ __forceinline__ void mma16816(float* d, uint32_t a0, uint32_t a1,
                                         uint32_t a2, uint32_t a3,
                                         uint32_t b0, uint32_t b1) {
    asm volatile(
        "mma.sync.aligned.m16n8k16.row.col.f32.bf16.bf16.f32 "
        "{%0,%1,%2,%3}, {%4,%5,%6,%7}, {%8,%9}, {%0,%1,%2,%3};"
        : "+f"(d[0]), "+f"(d[1]), "+f"(d[2]), "+f"(d[3])
        : "r"(a0), "r"(a1), "r"(a2), "r"(a3), "r"(b0), "r"(b1));
}
__device__ __forceinline__ void ldsm4(uint32_t& r0, uint32_t& r1, uint32_t& r2,
                                      uint32_t& r3, uint32_t addr) {
    asm volatile("ldmatrix.sync.aligned.m8n8.x4.shared.b16 {%0,%1,%2,%3}, [%4];"
        : "=r"(r0), "=r"(r1), "=r"(r2), "=r"(r3) : "r"(addr));
}
__device__ __forceinline__ void ldsm4t(uint32_t& r0, uint32_t& r1, uint32_t& r2,
                                       uint32_t& r3, uint32_t addr) {
    asm volatile("ldmatrix.sync.aligned.m8n8.x4.trans.shared.b16 {%0,%1,%2,%3}, [%4];"
        : "=r"(r0), "=r"(r1), "=r"(r2), "=r"(r3) : "r"(addr));
}
__device__ __forceinline__ void split_pack(float x0, float x1, uint32_t& h, uint32_t& l) {
    uint32_t hh;
    asm("cvt.rn.bf16x2.f32 %0, %1, %2;" : "=r"(hh) : "f"(x1), "f"(x0));
    float f0 = __uint_as_float(hh << 16);
    float f1 = __uint_as_float(hh & 0xffff0000u);
    float r0 = x0 - f0, r1 = x1 - f1;
    asm("cvt.rn.bf16x2.f32 %0, %1, %2;" : "=r"(l) : "f"(r1), "f"(r0));
    h = hh;
}
__device__ __forceinline__ void cpa16(uint32_t dst, const void* src) {
    asm volatile("cp.async.cg.shared.global [%0], [%1], 16;" :: "r"(dst), "l"(src));
}
#define CP_COMMIT()  asm volatile("cp.async.commit_group;" ::: "memory")
#define CP_WAIT(N)   asm volatile("cp.async.wait_group %0;" :: "n"(N) : "memory")

// ---------------------------------------------------------------------------
// Stage 0: split fp32 -> bf16 hi/lo  (2 float4 per thread for ILP)
// ---------------------------------------------------------------------------
__global__ __launch_bounds__(256) void conv_split(const float* __restrict__ in,
                                                  int which, int kind, int n4)
{
    __nv_bfloat16* hi = kind ? g_wh[which] : g_xh[which];
    __nv_bfloat16* lo = kind ? g_wl[which] : g_xl[which];
    int i0 = blockIdx.x * 512 + threadIdx.x;
#pragma unroll
    for (int u = 0; u < 2; u++) {
        int idx = i0 + u * 256;
        if (idx < n4) {
            float4 v = ((const float4*)in)[idx];
            uint32_t h0, l0, h1, l1;
            split_pack(v.x, v.y, h0, l0);
            split_pack(v.z, v.w, h1, l1);
            ((uint2*)hi)[idx] = make_uint2(h0, h1);
            ((uint2*)lo)[idx] = make_uint2(l0, l1);
        }
    }
}

// ---------------------------------------------------------------------------
// Stage 1: projection GEMM, cp.async double-buffered, K-tile 32
// CTA: 128 rows x 2 heads (N=128). grid (H/2, M/128, 3)
// ---------------------------------------------------------------------------
#define PX2 80    // X pitch: 32 halves + pad
#define PW  272   // W pitch: 128 halves + pad

static constexpr int PSXH = 0;
static constexpr int PSXL = PSXH + 128 * PX2;   // 10240
static constexpr int PSWH = PSXL + 128 * PX2;   // 20480
static constexpr int PSWL = PSWH + 32 * PW;     // 29184
static constexpr int PSTG = PSWL + 32 * PW;     // 37888 per stage
static constexpr int PROJ_SMEM = 2 * PSTG;      // 75776

__device__ __forceinline__ void proj_issue(
    uint32_t sbase, const __nv_bfloat16* Xh, const __nv_bfloat16* Xl,
    const __nv_bfloat16* Wh_, const __nv_bfloat16* Wl_,
    int m0, int h0, int k0, int t)
{
#pragma unroll
    for (int j = 0; j < 2; j++) {
        int idx = t + 256 * j;
        int r = idx >> 2, c8 = (idx & 3) * 8;
        size_t go = (size_t)(m0 + r) * DD + k0 + c8;
        uint32_t so = sbase + r * PX2 + c8 * 2;
        cpa16(so + PSXH, Xh + go);
        cpa16(so + PSXL, Xl + go);
    }
#pragma unroll
    for (int j = 0; j < 2; j++) {
        int idx = t + 256 * j;
        int r = idx >> 4, c8 = (idx & 15) * 8;
        int hh_ = h0 + (c8 >> 6), a = c8 & 63;
        size_t go = ((size_t)hh_ * DD + (k0 + r)) * AA + a;
        uint32_t so = sbase + r * PW + c8 * 2;
        cpa16(so + PSWH, Wh_ + go);
        cpa16(so + PSWL, Wl_ + go);
    }
}

__global__ __launch_bounds__(256, 2) void proj_mma(
    const float* __restrict__ bq, const float* __restrict__ bk,
    const float* __restrict__ bv)
{
    extern __shared__ char smc[];
    const uint32_t sb = smem_u32(smc);
    const int t = threadIdx.x, lane = t & 31, w = t >> 5;
    const int h0 = blockIdx.x * 2;
    const int m0 = blockIdx.y * 128;
    const int which = blockIdx.z;
    const float* bias = (which == 0) ? bq : (which == 1) ? bk : bv;

    const __nv_bfloat16* Xh = g_xh[which];
    const __nv_bfloat16* Xl = g_xl[which];
    const __nv_bfloat16* Wh_ = g_wh[which];
    const __nv_bfloat16* Wl_ = g_wl[which];
    __nv_bfloat16* Oh = g_ph[which];
    __nv_bfloat16* Ol = g_pl[which];

    const int lr  = lane & 7;
    const int grp = lane >> 3;
    const uint32_t a_row = 16 * w + lr + (grp & 1) * 8;
    const uint32_t a_cb  = (grp >> 1) * 16;
    const uint32_t wb_row = lr + (grp & 1) * 8;
    const uint32_t wb_cb  = (grp >> 1) * 16;

    float acc[16][4];
#pragma unroll
    for (int i = 0; i < 16; i++)
#pragma unroll
        for (int j = 0; j < 4; j++) acc[i][j] = 0.f;

    // prologue
    proj_issue(sb, Xh, Xl, Wh_, Wl_, m0, h0, 0, t);
    CP_COMMIT();

    const int NIT = DD / 32;  // 32
    for (int it = 0; it < NIT; it++) {
        __syncthreads();
        if (it + 1 < NIT) {
            proj_issue(sb + ((it + 1) & 1) * PSTG, Xh, Xl, Wh_, Wl_, m0, h0, (it + 1) * 32, t);
            CP_COMMIT();
            CP_WAIT(1);
        } else {
            CP_WAIT(0);
        }
        __syncthreads();

        const uint32_t st = sb + (it & 1) * PSTG;
        const uint32_t axh = st + PSXH + a_row * PX2 + a_cb;
        const uint32_t axl = st + PSXL + a_row * PX2 + a_cb;
#pragma unroll
        for (int ks = 0; ks < 2; ks++) {
            uint32_t xh0, xh1, xh2, xh3, xl0, xl1, xl2, xl3;
            ldsm4(xh0, xh1, xh2, xh3, axh + ks * 32);
            ldsm4(xl0, xl1, xl2, xl3, axl + ks * 32);
#pragma unroll
            for (int np = 0; np < 8; np++) {
                uint32_t wh0, wh1, wh2, wh3, wl0, wl1, wl2, wl3;
                uint32_t waddr = st + (ks * 16 + wb_row) * PW + np * 32 + wb_cb;
                ldsm4t(wh0, wh1, wh2, wh3, PSWH + waddr);
                ldsm4t(wl0, wl1, wl2, wl3, PSWL + waddr);
                mma16816(acc[2*np],   xh0, xh1, xh2, xh3, wh0, wh1);
                mma16816(acc[2*np+1], xh0, xh1, xh2, xh3, wh2, wh3);
                mma16816(acc[2*np],   xh0, xh1, xh2, xh3, wl0, wl1);
                mma16816(acc[2*np+1], xh0, xh1, xh2, xh3, wl2, wl3);
                mma16816(acc[2*np],   xl0, xl1, xl2, xl3, wh0, wh1);
                mma16816(acc[2*np+1], xl0, xl1, xl2, xl3, wh2, wh3);
            }
        }
    }

    // epilogue
    const int bidx = m0 / SS;
    const int srow = m0 % SS;
    const int rlo = lane >> 2;
    const int cp  = 2 * (lane & 3);
#pragma unroll
    for (int j = 0; j < 16; j++) {
        int n = 8 * j + cp;
        int hh_ = h0 + (n >> 6);
        int a = n & 63;
        float b0 = bias[hh_ * AA + a], b1 = bias[hh_ * AA + a + 1];
        int s0 = srow + 16 * w + rlo;
        size_t o0 = ((size_t)(bidx * HH + hh_) * SS + s0) * AA + a;
        size_t o1 = o0 + (size_t)8 * AA;
        uint32_t hv, lv;
        split_pack(acc[j][0] + b0, acc[j][1] + b1, hv, lv);
        *(uint32_t*)(Oh + o0) = hv; *(uint32_t*)(Ol + o0) = lv;
        split_pack(acc[j][2] + b0, acc[j][3] + b1, hv, lv);
        *(uint32_t*)(Oh + o1) = hv; *(uint32_t*)(Ol + o1) = lv;
    }
}

// ---------------------------------------------------------------------------
// Stage 2: flash attention, cp.async double-buffered K/V chunks of 64
// ---------------------------------------------------------------------------
#define PITCH 144

static constexpr int AKH = 0;
static constexpr int AKL = AKH + 64 * PITCH;    // 9216
static constexpr int AVH = AKL + 64 * PITCH;    // 18432
static constexpr int AVL = AVH + 64 * PITCH;    // 27648
static constexpr int ASTG = AVL + 64 * PITCH;   // 36864 per stage
static constexpr int ASQH = 2 * ASTG;           // 73728
static constexpr int ASQL = ASQH + 128 * PITCH; // 92160
static constexpr int ATTN_SMEM = ASQL + 128 * PITCH; // 110592

__device__ __forceinline__ void attn_issue(
    uint32_t sbase, const __nv_bfloat16* kh, const __nv_bfloat16* kl,
    const __nv_bfloat16* vh, const __nv_bfloat16* vl, int t)
{
#pragma unroll
    for (int j = 0; j < 2; j++) {
        int idx = t + 256 * j;
        int r = idx >> 3, c8 = (idx & 7) * 8;
        size_t go = (size_t)r * AA + c8;
        uint32_t so = sbase + r * PITCH + c8 * 2;
        cpa16(so + AKH, kh + go);
        cpa16(so + AKL, kl + go);
        cpa16(so + AVH, vh + go);
        cpa16(so + AVL, vl + go);
    }
}

__global__ __launch_bounds__(256, 2) void attn_mma(float* __restrict__ out)
{
    extern __shared__ char smc[];
    const uint32_t sb = smem_u32(smc);
    const int t = threadIdx.x, lane = t & 31, w = t >> 5;
    const int qt = blockIdx.x, h = blockIdx.y, b = blockIdx.z;
    const size_t bh = (size_t)(b * HH + h) * SS;

    const __nv_bfloat16* kh0 = g_ph[1] + bh * AA;
    const __nv_bfloat16* kl0 = g_pl[1] + bh * AA;
    const __nv_bfloat16* vh0 = g_ph[2] + bh * AA;
    const __nv_bfloat16* vl0 = g_pl[2] + bh * AA;

    // prologue: issue chunk 0
    attn_issue(sb, kh0, kl0, vh0, vl0, t);
    CP_COMMIT();

    // load Q (regular stores, separate region)
    {
        const __nv_bfloat16* qh = g_ph[0] + (bh + qt * 128) * AA;
        const __nv_bfloat16* ql = g_pl[0] + (bh + qt * 128) * AA;
#pragma unroll
        for (int j = 0; j < 4; j++) {
            int idx = t + 256 * j;
            int r = idx >> 3, c = (idx & 7) * 8;
            *(uint4*)(smc + ASQH + r * PITCH + c * 2) = *(const uint4*)(qh + (size_t)r * AA + c);
            *(uint4*)(smc + ASQL + r * PITCH + c * 2) = *(const uint4*)(ql + (size_t)r * AA + c);
        }
    }

    const int lr  = lane & 7;
    const int grp = lane >> 3;
    const uint32_t a_row = 16 * w + lr + (grp & 1) * 8;
    const uint32_t a_cb  = (grp >> 1) * 16;
    const uint32_t kb_row = lr + (grp >> 1) * 8;
    const uint32_t kb_cb  = (grp & 1) * 16;
    const uint32_t vb_row = lr + (grp & 1) * 8;
    const uint32_t vb_cb  = (grp >> 1) * 16;

    const uint32_t aqh = sb + ASQH + a_row * PITCH + a_cb;
    const uint32_t aql = sb + ASQL + a_row * PITCH + a_cb;

    float oacc[8][4];
#pragma unroll
    for (int i = 0; i < 8; i++)
#pragma unroll
        for (int j = 0; j < 4; j++) oacc[i][j] = 0.f;
    float lA = 0.f, lB = 0.f, CA = 0.f, CB = 0.f;

    const int NIT = SS / 64;  // 32
    for (int kt = 0; kt < NIT; kt++) {
        __syncthreads();
        if (kt + 1 < NIT) {
            size_t ko = (size_t)(kt + 1) * 64 * AA;
            attn_issue(sb + ((kt + 1) & 1) * ASTG, kh0 + ko, kl0 + ko, vh0 + ko, vl0 + ko, t);
            CP_COMMIT();
            CP_WAIT(1);
        } else {
            CP_WAIT(0);
        }
        __syncthreads();

        const uint32_t st = sb + (kt & 1) * ASTG;

        float sacc[8][4];
#pragma unroll
        for (int i = 0; i < 8; i++)
#pragma unroll
            for (int j = 0; j < 4; j++) sacc[i][j] = 0.f;

#pragma unroll
        for (int ks = 0; ks < 4; ks++) {
            uint32_t qh0, qh1, qh2, qh3, ql0, ql1, ql2, ql3;
            ldsm4(qh0, qh1, qh2, qh3, aqh + ks * 32);
            ldsm4(ql0, ql1, ql2, ql3, aql + ks * 32);
#pragma unroll
            for (int np = 0; np < 4; np++) {
                uint32_t kh0r, kh1r, kh2r, kh3r, kl0r, kl1r, kl2r, kl3r;
                uint32_t kaddr = st + (np * 16 + kb_row) * PITCH + ks * 32 + kb_cb;
                ldsm4(kh0r, kh1r, kh2r, kh3r, AKH + kaddr);
                ldsm4(kl0r, kl1r, kl2r, kl3r, AKL + kaddr);
                mma16816(sacc[2*np],   qh0, qh1, qh2, qh3, kh0r, kh1r);
                mma16816(sacc[2*np+1], qh0, qh1, qh2, qh3, kh2r, kh3r);
                mma16816(sacc[2*np],   qh0, qh1, qh2, qh3, kl0r, kl1r);
                mma16816(sacc[2*np+1], qh0, qh1, qh2, qh3, kl2r, kl3r);
                mma16816(sacc[2*np],   ql0, ql1, ql2, ql3, kh0r, kh1r);
                mma16816(sacc[2*np+1], ql0, ql1, ql2, ql3, kh2r, kh3r);
            }
        }

        if (kt == 0) {
            float mA = -1e30f, mB = -1e30f;
#pragma unroll
            for (int i = 0; i < 8; i++) {
                mA = fmaxf(mA, fmaxf(sacc[i][0], sacc[i][1]));
                mB = fmaxf(mB, fmaxf(sacc[i][2], sacc[i][3]));
            }
            mA = fmaxf(mA, __shfl_xor_sync(0xffffffffu, mA, 1));
            mA = fmaxf(mA, __shfl_xor_sync(0xffffffffu, mA, 2));
            mB = fmaxf(mB, __shfl_xor_sync(0xffffffffu, mB, 1));
            mB = fmaxf(mB, __shfl_xor_sync(0xffffffffu, mB, 2));
            CA = mA; CB = mB;
        }
#pragma unroll
        for (int i = 0; i < 8; i++) {
            sacc[i][0] = __expf(sacc[i][0] - CA);
            sacc[i][1] = __expf(sacc[i][1] - CA);
            sacc[i][2] = __expf(sacc[i][2] - CB);
            sacc[i][3] = __expf(sacc[i][3] - CB);
            lA += sacc[i][0] + sacc[i][1];
            lB += sacc[i][2] + sacc[i][3];
        }

#pragma unroll
        for (int ks = 0; ks < 4; ks++) {
            uint32_t ph0, ph1, ph2, ph3, pl0, pl1, pl2, pl3;
            split_pack(sacc[2*ks][0],   sacc[2*ks][1],   ph0, pl0);
            split_pack(sacc[2*ks][2],   sacc[2*ks][3],   ph1, pl1);
            split_pack(sacc[2*ks+1][0], sacc[2*ks+1][1], ph2, pl2);
            split_pack(sacc[2*ks+1][2], sacc[2*ks+1][3], ph3, pl3);
#pragma unroll
            for (int np = 0; np < 4; np++) {
                uint32_t vh0r, vh1r, vh2r, vh3r, vl0r, vl1r, vl2r, vl3r;
                uint32_t vaddr = st + (ks * 16 + vb_row) * PITCH + np * 32 + vb_cb;
                ldsm4t(vh0r, vh1r, vh2r, vh3r, AVH + vaddr);
                ldsm4t(vl0r, vl1r, vl2r, vl3r, AVL + vaddr);
                mma16816(oacc[2*np],   ph0, ph1, ph2, ph3, vh0r, vh1r);
                mma16816(oacc[2*np+1], ph0, ph1, ph2, ph3, vh2r, vh3r);
                mma16816(oacc[2*np],   ph0, ph1, ph2, ph3, vl0r, vl1r);
                mma16816(oacc[2*np+1], ph0, ph1, ph2, ph3, vl2r, vl3r);
                mma16816(oacc[2*np],   pl0, pl1, pl2, pl3, vh0r, vh1r);
                mma16816(oacc[2*np+1], pl0, pl1, pl2, pl3, vh2r, vh3r);
            }
        }
    }

    lA += __shfl_xor_sync(0xffffffffu, lA, 1);
    lA += __shfl_xor_sync(0xffffffffu, lA, 2);
    lB += __shfl_xor_sync(0xffffffffu, lB, 1);
    lB += __shfl_xor_sync(0xffffffffu, lB, 2);
    float invA = 1.f / lA, invB = 1.f / lB;

    int rA = qt * 128 + 16 * w + (lane >> 2);
    int col = 2 * (lane & 3);
    float* oA = out + ((size_t)(b * SS + rA)) * (HH * AA) + h * AA + col;
    float* oB = oA + 8 * (HH * AA);
#pragma unroll
    for (int j = 0; j < 8; j++) {
        float2 vA = make_float2(oacc[j][0] * invA, oacc[j][1] * invA);
        float2 vB = make_float2(oacc[j][2] * invB, oacc[j][3] * invB);
        *(float2*)(oA + j * 8) = vA;
        *(float2*)(oB + j * 8) = vB;
    }
}

// ---------------------------------------------------------------------------

extern "C" void kernel_launch(void* const* d_in, const int* in_sizes, int n_in,
                              void* d_out, int out_size)
{
    const float* q  = (const float*)d_in[0];
    const float* k  = (const float*)d_in[1];
    const float* v  = (const float*)d_in[2];
    const float* Wq = (const float*)d_in[3];
    const float* bq = (const float*)d_in[4];
    const float* Wk = (const float*)d_in[5];
    const float* bk = (const float*)d_in[6];
    const float* Wv = (const float*)d_in[7];
    const float* bv = (const float*)d_in[8];
    float* out = (float*)d_out;

    cudaFuncSetAttribute(proj_mma, cudaFuncAttributeMaxDynamicSharedMemorySize, PROJ_SMEM);
    cudaFuncSetAttribute(attn_mma, cudaFuncAttributeMaxDynamicSharedMemorySize, ATTN_SMEM);

    conv_split<<<NX/4/512, 256>>>(q, 0, 0, NX/4);
    conv_split<<<NX/4/512, 256>>>(k, 1, 0, NX/4);
    conv_split<<<NX/4/512, 256>>>(v, 2, 0, NX/4);
    conv_split<<<NW/4/512, 256>>>(Wq, 0, 1, NW/4);
    conv_split<<<NW/4/512, 256>>>(Wk, 1, 1, NW/4);
    conv_split<<<NW/4/512, 256>>>(Wv, 2, 1, NW/4);

    dim3 pgrid(HH/2, 64, 3);
    proj_mma<<<pgrid, 256, PROJ_SMEM>>>(bq, bk, bv);

    dim3 agrid(16, 16, 4);
    attn_mma<<<agrid, 256, ATTN_SMEM>>>(out);
}

// round 6
// speedup vs baseline: 3.0302x; 1.0021x over previous
#include <cuda_runtime.h>
#include <cuda_bf16.h>
#include <cstdint>
#include <cstddef>

#define BB 4
#define SS 2048
#define DD 1024
#define HH 16
#define AA 64

#define NX (BB*SS*DD)
#define NW (HH*DD*AA)
#define NP (BB*HH*SS*AA)

__device__ __nv_bfloat16 g_xh[3][NX], g_xl[3][NX];
__device__ __nv_bfloat16 g_wh[3][NW], g_wl[3][NW];
__device__ __nv_bfloat16 g_ph[3][NP], g_pl[3][NP];

// ---------------------------------------------------------------------------
__device__ __forceinline__ uint32_t smem_u32(const void* p) {
    uint32_t a;
    asm("{ .reg .u64 t; cvta.to.shared.u64 t, %1; cvt.u32.u64 %0, t; }" : "=r"(a) : "l"(p));
    return a;
}
__device__ __forceinline__ void mma16816(float* d, uint32_t a0, uint32_t a1,
                                         uint32_t a2, uint32_t a3,
                                         uint32_t b0, uint32_t b1) {
    asm volatile(
        "mma.sync.aligned.m16n8k16.row.col.f32.bf16.bf16.f32 "
        "{%0,%1,%2,%3}, {%4,%5,%6,%7}, {%8,%9}, {%0,%1,%2,%3};"
        : "+f"(d[0]), "+f"(d[1]), "+f"(d[2]), "+f"(d[3])
        : "r"(a0), "r"(a1), "r"(a2), "r"(a3), "r"(b0), "r"(b1));
}
__device__ __forceinline__ void ldsm4(uint32_t& r0, uint32_t& r1, uint32_t& r2,
                                      uint32_t& r3, uint32_t addr) {
    asm volatile("ldmatrix.sync.aligned.m8n8.x4.shared.b16 {%0,%1,%2,%3}, [%4];"
        : "=r"(r0), "=r"(r1), "=r"(r2), "=r"(r3) : "r"(addr));
}
__device__ __forceinline__ void ldsm4t(uint32_t& r0, uint32_t& r1, uint32_t& r2,
                                       uint32_t& r3, uint32_t addr) {
    asm volatile("ldmatrix.sync.aligned.m8n8.x4.trans.shared.b16 {%0,%1,%2,%3}, [%4];"
        : "=r"(r0), "=r"(r1), "=r"(r2), "=r"(r3) : "r"(addr));
}
__device__ __forceinline__ void split_pack(float x0, float x1, uint32_t& h, uint32_t& l) {
    uint32_t hh;
    asm("cvt.rn.bf16x2.f32 %0, %1, %2;" : "=r"(hh) : "f"(x1), "f"(x0));
    float f0 = __uint_as_float(hh << 16);
    float f1 = __uint_as_float(hh & 0xffff0000u);
    float r0 = x0 - f0, r1 = x1 - f1;
    asm("cvt.rn.bf16x2.f32 %0, %1, %2;" : "=r"(l) : "f"(r1), "f"(r0));
    h = hh;
}
__device__ __forceinline__ void cpa16(uint32_t dst, const void* src) {
    asm volatile("cp.async.cg.shared.global [%0], [%1], 16;" :: "r"(dst), "l"(src));
}
#define CP_COMMIT()  asm volatile("cp.async.commit_group;" ::: "memory")
#define CP_WAIT(N)   asm volatile("cp.async.wait_group %0;" :: "n"(N) : "memory")

// ---------------------------------------------------------------------------
// Stage 0: split fp32 -> bf16 hi/lo  (2 float4 per thread for ILP)
// ---------------------------------------------------------------------------
__global__ __launch_bounds__(256) void conv_split(const float* __restrict__ in,
                                                  int which, int kind, int n4)
{
    __nv_bfloat16* hi = kind ? g_wh[which] : g_xh[which];
    __nv_bfloat16* lo = kind ? g_wl[which] : g_xl[which];
    int i0 = blockIdx.x * 512 + threadIdx.x;
#pragma unroll
    for (int u = 0; u < 2; u++) {
        int idx = i0 + u * 256;
        if (idx < n4) {
            float4 v = ((const float4*)in)[idx];
            uint32_t h0, l0, h1, l1;
            split_pack(v.x, v.y, h0, l0);
            split_pack(v.z, v.w, h1, l1);
            ((uint2*)hi)[idx] = make_uint2(h0, h1);
            ((uint2*)lo)[idx] = make_uint2(l0, l1);
        }
    }
}

// ---------------------------------------------------------------------------
// Stage 1: projection GEMM, cp.async double-buffered, K-tile 32
// CTA: 128 rows x 2 heads (N=128). grid (H/2, M/128, 3)
// ---------------------------------------------------------------------------
#define PX2 80    // X pitch: 32 halves + pad
#define PW  272   // W pitch: 128 halves + pad

static constexpr int PSXH = 0;
static constexpr int PSXL = PSXH + 128 * PX2;   // 10240
static constexpr int PSWH = PSXL + 128 * PX2;   // 20480
static constexpr int PSWL = PSWH + 32 * PW;     // 29184
static constexpr int PSTG = PSWL + 32 * PW;     // 37888 per stage
static constexpr int PROJ_SMEM = 2 * PSTG;      // 75776

__device__ __forceinline__ void proj_issue(
    uint32_t sbase, const __nv_bfloat16* Xh, const __nv_bfloat16* Xl,
    const __nv_bfloat16* Wh_, const __nv_bfloat16* Wl_,
    int m0, int h0, int k0, int t)
{
#pragma unroll
    for (int j = 0; j < 2; j++) {
        int idx = t + 256 * j;
        int r = idx >> 2, c8 = (idx & 3) * 8;
        size_t go = (size_t)(m0 + r) * DD + k0 + c8;
        uint32_t so = sbase + r * PX2 + c8 * 2;
        cpa16(so + PSXH, Xh + go);
        cpa16(so + PSXL, Xl + go);
    }
#pragma unroll
    for (int j = 0; j < 2; j++) {
        int idx = t + 256 * j;
        int r = idx >> 4, c8 = (idx & 15) * 8;
        int hh_ = h0 + (c8 >> 6), a = c8 & 63;
        size_t go = ((size_t)hh_ * DD + (k0 + r)) * AA + a;
        uint32_t so = sbase + r * PW + c8 * 2;
        cpa16(so + PSWH, Wh_ + go);
        cpa16(so + PSWL, Wl_ + go);
    }
}

__global__ __launch_bounds__(256, 2) void proj_mma(
    const float* __restrict__ bq, const float* __restrict__ bk,
    const float* __restrict__ bv)
{
    extern __shared__ char smc[];
    const uint32_t sb = smem_u32(smc);
    const int t = threadIdx.x, lane = t & 31, w = t >> 5;
    const int h0 = blockIdx.x * 2;
    const int m0 = blockIdx.y * 128;
    const int which = blockIdx.z;
    const float* bias = (which == 0) ? bq : (which == 1) ? bk : bv;

    const __nv_bfloat16* Xh = g_xh[which];
    const __nv_bfloat16* Xl = g_xl[which];
    const __nv_bfloat16* Wh_ = g_wh[which];
    const __nv_bfloat16* Wl_ = g_wl[which];
    __nv_bfloat16* Oh = g_ph[which];
    __nv_bfloat16* Ol = g_pl[which];

    const int lr  = lane & 7;
    const int grp = lane >> 3;
    const uint32_t a_row = 16 * w + lr + (grp & 1) * 8;
    const uint32_t a_cb  = (grp >> 1) * 16;
    const uint32_t wb_row = lr + (grp & 1) * 8;
    const uint32_t wb_cb  = (grp >> 1) * 16;

    float acc[16][4];
#pragma unroll
    for (int i = 0; i < 16; i++)
#pragma unroll
        for (int j = 0; j < 4; j++) acc[i][j] = 0.f;

    // prologue
    proj_issue(sb, Xh, Xl, Wh_, Wl_, m0, h0, 0, t);
    CP_COMMIT();

    const int NIT = DD / 32;  // 32
    for (int it = 0; it < NIT; it++) {
        __syncthreads();
        if (it + 1 < NIT) {
            proj_issue(sb + ((it + 1) & 1) * PSTG, Xh, Xl, Wh_, Wl_, m0, h0, (it + 1) * 32, t);
            CP_COMMIT();
            CP_WAIT(1);
        } else {
            CP_WAIT(0);
        }
        __syncthreads();

        const uint32_t st = sb + (it & 1) * PSTG;
        const uint32_t axh = st + PSXH + a_row * PX2 + a_cb;
        const uint32_t axl = st + PSXL + a_row * PX2 + a_cb;
#pragma unroll
        for (int ks = 0; ks < 2; ks++) {
            uint32_t xh0, xh1, xh2, xh3, xl0, xl1, xl2, xl3;
            ldsm4(xh0, xh1, xh2, xh3, axh + ks * 32);
            ldsm4(xl0, xl1, xl2, xl3, axl + ks * 32);
#pragma unroll
            for (int np = 0; np < 8; np++) {
                uint32_t wh0, wh1, wh2, wh3, wl0, wl1, wl2, wl3;
                uint32_t waddr = st + (ks * 16 + wb_row) * PW + np * 32 + wb_cb;
                ldsm4t(wh0, wh1, wh2, wh3, PSWH + waddr);
                ldsm4t(wl0, wl1, wl2, wl3, PSWL + waddr);
                mma16816(acc[2*np],   xh0, xh1, xh2, xh3, wh0, wh1);
                mma16816(acc[2*np+1], xh0, xh1, xh2, xh3, wh2, wh3);
                mma16816(acc[2*np],   xh0, xh1, xh2, xh3, wl0, wl1);
                mma16816(acc[2*np+1], xh0, xh1, xh2, xh3, wl2, wl3);
                mma16816(acc[2*np],   xl0, xl1, xl2, xl3, wh0, wh1);
                mma16816(acc[2*np+1], xl0, xl1, xl2, xl3, wh2, wh3);
            }
        }
    }

    // epilogue
    const int bidx = m0 / SS;
    const int srow = m0 % SS;
    const int rlo = lane >> 2;
    const int cp  = 2 * (lane & 3);
#pragma unroll
    for (int j = 0; j < 16; j++) {
        int n = 8 * j + cp;
        int hh_ = h0 + (n >> 6);
        int a = n & 63;
        float b0 = bias[hh_ * AA + a], b1 = bias[hh_ * AA + a + 1];
        int s0 = srow + 16 * w + rlo;
        size_t o0 = ((size_t)(bidx * HH + hh_) * SS + s0) * AA + a;
        size_t o1 = o0 + (size_t)8 * AA;
        uint32_t hv, lv;
        split_pack(acc[j][0] + b0, acc[j][1] + b1, hv, lv);
        *(uint32_t*)(Oh + o0) = hv; *(uint32_t*)(Ol + o0) = lv;
        split_pack(acc[j][2] + b0, acc[j][3] + b1, hv, lv);
        *(uint32_t*)(Oh + o1) = hv; *(uint32_t*)(Ol + o1) = lv;
    }
}

// ---------------------------------------------------------------------------
// Stage 2: flash attention, cp.async double-buffered K/V chunks of 64
// ---------------------------------------------------------------------------
#define PITCH 144

static constexpr int AKH = 0;
static constexpr int AKL = AKH + 64 * PITCH;    // 9216
static constexpr int AVH = AKL + 64 * PITCH;    // 18432
static constexpr int AVL = AVH + 64 * PITCH;    // 27648
static constexpr int ASTG = AVL + 64 * PITCH;   // 36864 per stage
static constexpr int ASQH = 2 * ASTG;           // 73728
static constexpr int ASQL = ASQH + 128 * PITCH; // 92160
static constexpr int ATTN_SMEM = ASQL + 128 * PITCH; // 110592

__device__ __forceinline__ void attn_issue(
    uint32_t sbase, const __nv_bfloat16* kh, const __nv_bfloat16* kl,
    const __nv_bfloat16* vh, const __nv_bfloat16* vl, int t)
{
#pragma unroll
    for (int j = 0; j < 2; j++) {
        int idx = t + 256 * j;
        int r = idx >> 3, c8 = (idx & 7) * 8;
        size_t go = (size_t)r * AA + c8;
        uint32_t so = sbase + r * PITCH + c8 * 2;
        cpa16(so + AKH, kh + go);
        cpa16(so + AKL, kl + go);
        cpa16(so + AVH, vh + go);
        cpa16(so + AVL, vl + go);
    }
}

__global__ __launch_bounds__(256, 2) void attn_mma(float* __restrict__ out)
{
    extern __shared__ char smc[];
    const uint32_t sb = smem_u32(smc);
    const int t = threadIdx.x, lane = t & 31, w = t >> 5;
    const int qt = blockIdx.x, h = blockIdx.y, b = blockIdx.z;
    const size_t bh = (size_t)(b * HH + h) * SS;

    const __nv_bfloat16* kh0 = g_ph[1] + bh * AA;
    const __nv_bfloat16* kl0 = g_pl[1] + bh * AA;
    const __nv_bfloat16* vh0 = g_ph[2] + bh * AA;
    const __nv_bfloat16* vl0 = g_pl[2] + bh * AA;

    // prologue: issue chunk 0
    attn_issue(sb, kh0, kl0, vh0, vl0, t);
    CP_COMMIT();

    // load Q (regular stores, separate region)
    {
        const __nv_bfloat16* qh = g_ph[0] + (bh + qt * 128) * AA;
        const __nv_bfloat16* ql = g_pl[0] + (bh + qt * 128) * AA;
#pragma unroll
        for (int j = 0; j < 4; j++) {
            int idx = t + 256 * j;
            int r = idx >> 3, c = (idx & 7) * 8;
            *(uint4*)(smc + ASQH + r * PITCH + c * 2) = *(const uint4*)(qh + (size_t)r * AA + c);
            *(uint4*)(smc + ASQL + r * PITCH + c * 2) = *(const uint4*)(ql + (size_t)r * AA + c);
        }
    }

    const int lr  = lane & 7;
    const int grp = lane >> 3;
    const uint32_t a_row = 16 * w + lr + (grp & 1) * 8;
    const uint32_t a_cb  = (grp >> 1) * 16;
    const uint32_t kb_row = lr + (grp >> 1) * 8;
    const uint32_t kb_cb  = (grp & 1) * 16;
    const uint32_t vb_row = lr + (grp & 1) * 8;
    const uint32_t vb_cb  = (grp >> 1) * 16;

    const uint32_t aqh = sb + ASQH + a_row * PITCH + a_cb;
    const uint32_t aql = sb + ASQL + a_row * PITCH + a_cb;

    float oacc[8][4];
#pragma unroll
    for (int i = 0; i < 8; i++)
#pragma unroll
        for (int j = 0; j < 4; j++) oacc[i][j] = 0.f;
    float lA = 0.f, lB = 0.f, CA = 0.f, CB = 0.f;

    const int NIT = SS / 64;  // 32
    for (int kt = 0; kt < NIT; kt++) {
        __syncthreads();
        if (kt + 1 < NIT) {
            size_t ko = (size_t)(kt + 1) * 64 * AA;
            attn_issue(sb + ((kt + 1) & 1) * ASTG, kh0 + ko, kl0 + ko, vh0 + ko, vl0 + ko, t);
            CP_COMMIT();
            CP_WAIT(1);
        } else {
            CP_WAIT(0);
        }
        __syncthreads();

        const uint32_t st = sb + (kt & 1) * ASTG;

        float sacc[8][4];
#pragma unroll
        for (int i = 0; i < 8; i++)
#pragma unroll
            for (int j = 0; j < 4; j++) sacc[i][j] = 0.f;

#pragma unroll
        for (int ks = 0; ks < 4; ks++) {
            uint32_t qh0, qh1, qh2, qh3, ql0, ql1, ql2, ql3;
            ldsm4(qh0, qh1, qh2, qh3, aqh + ks * 32);
            ldsm4(ql0, ql1, ql2, ql3, aql + ks * 32);
#pragma unroll
            for (int np = 0; np < 4; np++) {
                uint32_t kh0r, kh1r, kh2r, kh3r, kl0r, kl1r, kl2r, kl3r;
                uint32_t kaddr = st + (np * 16 + kb_row) * PITCH + ks * 32 + kb_cb;
                ldsm4(kh0r, kh1r, kh2r, kh3r, AKH + kaddr);
                ldsm4(kl0r, kl1r, kl2r, kl3r, AKL + kaddr);
                mma16816(sacc[2*np],   qh0, qh1, qh2, qh3, kh0r, kh1r);
                mma16816(sacc[2*np+1], qh0, qh1, qh2, qh3, kh2r, kh3r);
                mma16816(sacc[2*np],   qh0, qh1, qh2, qh3, kl0r, kl1r);
                mma16816(sacc[2*np+1], qh0, qh1, qh2, qh3, kl2r, kl3r);
                mma16816(sacc[2*np],   ql0, ql1, ql2, ql3, kh0r, kh1r);
                mma16816(sacc[2*np+1], ql0, ql1, ql2, ql3, kh2r, kh3r);
            }
        }

        if (kt == 0) {
            float mA = -1e30f, mB = -1e30f;
#pragma unroll
            for (int i = 0; i < 8; i++) {
                mA = fmaxf(mA, fmaxf(sacc[i][0], sacc[i][1]));
                mB = fmaxf(mB, fmaxf(sacc[i][2], sacc[i][3]));
            }
            mA = fmaxf(mA, __shfl_xor_sync(0xffffffffu, mA, 1));
            mA = fmaxf(mA, __shfl_xor_sync(0xffffffffu, mA, 2));
            mB = fmaxf(mB, __shfl_xor_sync(0xffffffffu, mB, 1));
            mB = fmaxf(mB, __shfl_xor_sync(0xffffffffu, mB, 2));
            CA = mA; CB = mB;
        }
#pragma unroll
        for (int i = 0; i < 8; i++) {
            sacc[i][0] = __expf(sacc[i][0] - CA);
            sacc[i][1] = __expf(sacc[i][1] - CA);
            sacc[i][2] = __expf(sacc[i][2] - CB);
            sacc[i][3] = __expf(sacc[i][3] - CB);
            lA += sacc[i][0] + sacc[i][1];
            lB += sacc[i][2] + sacc[i][3];
        }

#pragma unroll
        for (int ks = 0; ks < 4; ks++) {
            uint32_t ph0, ph1, ph2, ph3, pl0, pl1, pl2, pl3;
            split_pack(sacc[2*ks][0],   sacc[2*ks][1],   ph0, pl0);
            split_pack(sacc[2*ks][2],   sacc[2*ks][3],   ph1, pl1);
            split_pack(sacc[2*ks+1][0], sacc[2*ks+1][1], ph2, pl2);
            split_pack(sacc[2*ks+1][2], sacc[2*ks+1][3], ph3, pl3);
#pragma unroll
            for (int np = 0; np < 4; np++) {
                uint32_t vh0r, vh1r, vh2r, vh3r, vl0r, vl1r, vl2r, vl3r;
                uint32_t vaddr = st + (ks * 16 + vb_row) * PITCH + np * 32 + vb_cb;
                ldsm4t(vh0r, vh1r, vh2r, vh3r, AVH + vaddr);
                ldsm4t(vl0r, vl1r, vl2r, vl3r, AVL + vaddr);
                mma16816(oacc[2*np],   ph0, ph1, ph2, ph3, vh0r, vh1r);
                mma16816(oacc[2*np+1], ph0, ph1, ph2, ph3, vh2r, vh3r);
                mma16816(oacc[2*np],   ph0, ph1, ph2, ph3, vl0r, vl1r);
                mma16816(oacc[2*np+1], ph0, ph1, ph2, ph3, vl2r, vl3r);
                mma16816(oacc[2*np],   pl0, pl1, pl2, pl3, vh0r, vh1r);
                mma16816(oacc[2*np+1], pl0, pl1, pl2, pl3, vh2r, vh3r);
            }
        }
    }

    lA += __shfl_xor_sync(0xffffffffu, lA, 1);
    lA += __shfl_xor_sync(0xffffffffu, lA, 2);
    lB += __shfl_xor_sync(0xffffffffu, lB, 1);
    lB += __shfl_xor_sync(0xffffffffu, lB, 2);
    float invA = 1.f / lA, invB = 1.f / lB;

    int rA = qt * 128 + 16 * w + (lane >> 2);
    int col = 2 * (lane & 3);
    float* oA = out + ((size_t)(b * SS + rA)) * (HH * AA) + h * AA + col;
    float* oB = oA + 8 * (HH * AA);
#pragma unroll
    for (int j = 0; j < 8; j++) {
        float2 vA = make_float2(oacc[j][0] * invA, oacc[j][1] * invA);
        float2 vB = make_float2(oacc[j][2] * invB, oacc[j][3] * invB);
        *(float2*)(oA + j * 8) = vA;
        *(float2*)(oB + j * 8) = vB;
    }
}

// ---------------------------------------------------------------------------

extern "C" void kernel_launch(void* const* d_in, const int* in_sizes, int n_in,
                              void* d_out, int out_size)
{
    const float* q  = (const float*)d_in[0];
    const float* k  = (const float*)d_in[1];
    const float* v  = (const float*)d_in[2];
    const float* Wq = (const float*)d_in[3];
    const float* bq = (const float*)d_in[4];
    const float* Wk = (const float*)d_in[5];
    const float* bk = (const float*)d_in[6];
    const float* Wv = (const float*)d_in[7];
    const float* bv = (const float*)d_in[8];
    float* out = (float*)d_out;

    cudaFuncSetAttribute(proj_mma, cudaFuncAttributeMaxDynamicSharedMemorySize, PROJ_SMEM);
    cudaFuncSetAttribute(attn_mma, cudaFuncAttributeMaxDynamicSharedMemorySize, ATTN_SMEM);

    conv_split<<<NX/4/512, 256>>>(q, 0, 0, NX/4);
    conv_split<<<NX/4/512, 256>>>(k, 1, 0, NX/4);
    conv_split<<<NX/4/512, 256>>>(v, 2, 0, NX/4);
    conv_split<<<NW/4/512, 256>>>(Wq, 0, 1, NW/4);
    conv_split<<<NW/4/512, 256>>>(Wk, 1, 1, NW/4);
    conv_split<<<NW/4/512, 256>>>(Wv, 2, 1, NW/4);

    dim3 pgrid(HH/2, 64, 3);
    proj_mma<<<pgrid, 256, PROJ_SMEM>>>(bq, bk, bv);

    dim3 agrid(16, 16, 4);
    attn_mma<<<agrid, 256, ATTN_SMEM>>>(out);
}

// round 7
// speedup vs baseline: 3.0308x; 1.0002x over previous
#include <cuda_runtime.h>
#include <cuda_bf16.h>
#include <cstdint>
#include <cstddef>

#define BB 4
#define SS 2048
#define DD 1024
#define HH 16
#define AA 64

#define NX (BB*SS*DD)
#define NW (HH*DD*AA)
#define NP (BB*HH*SS*AA)

__device__ __nv_bfloat16 g_xh[3][NX], g_xl[3][NX];
__device__ __nv_bfloat16 g_wh[3][NW], g_wl[3][NW];
__device__ __nv_bfloat16 g_ph[3][NP], g_pl[3][NP];

// ---------------------------------------------------------------------------
__device__ __forceinline__ uint32_t smem_u32(const void* p) {
    uint32_t a;
    asm("{ .reg .u64 t; cvta.to.shared.u64 t, %1; cvt.u32.u64 %0, t; }" : "=r"(a) : "l"(p));
    return a;
}
__device__ __forceinline__ void mma16816(float* d, uint32_t a0, uint32_t a1,
                                         uint32_t a2, uint32_t a3,
                                         uint32_t b0, uint32_t b1) {
    asm volatile(
        "mma.sync.aligned.m16n8k16.row.col.f32.bf16.bf16.f32 "
        "{%0,%1,%2,%3}, {%4,%5,%6,%7}, {%8,%9}, {%0,%1,%2,%3};"
        : "+f"(d[0]), "+f"(d[1]), "+f"(d[2]), "+f"(d[3])
        : "r"(a0), "r"(a1), "r"(a2), "r"(a3), "r"(b0), "r"(b1));
}
__device__ __forceinline__ void ldsm4(uint32_t& r0, uint32_t& r1, uint32_t& r2,
                                      uint32_t& r3, uint32_t addr) {
    asm volatile("ldmatrix.sync.aligned.m8n8.x4.shared.b16 {%0,%1,%2,%3}, [%4];"
        : "=r"(r0), "=r"(r1), "=r"(r2), "=r"(r3) : "r"(addr));
}
__device__ __forceinline__ void ldsm4t(uint32_t& r0, uint32_t& r1, uint32_t& r2,
                                       uint32_t& r3, uint32_t addr) {
    asm volatile("ldmatrix.sync.aligned.m8n8.x4.trans.shared.b16 {%0,%1,%2,%3}, [%4];"
        : "=r"(r0), "=r"(r1), "=r"(r2), "=r"(r3) : "r"(addr));
}
__device__ __forceinline__ void split_pack(float x0, float x1, uint32_t& h, uint32_t& l) {
    uint32_t hh;
    asm("cvt.rn.bf16x2.f32 %0, %1, %2;" : "=r"(hh) : "f"(x1), "f"(x0));
    float f0 = __uint_as_float(hh << 16);
    float f1 = __uint_as_float(hh & 0xffff0000u);
    float r0 = x0 - f0, r1 = x1 - f1;
    asm("cvt.rn.bf16x2.f32 %0, %1, %2;" : "=r"(l) : "f"(r1), "f"(r0));
    h = hh;
}
__device__ __forceinline__ void cpa16(uint32_t dst, const void* src) {
    asm volatile("cp.async.cg.shared.global [%0], [%1], 16;" :: "r"(dst), "l"(src));
}
#define CP_COMMIT()  asm volatile("cp.async.commit_group;" ::: "memory")
#define CP_WAIT(N)   asm volatile("cp.async.wait_group %0;" :: "n"(N) : "memory")

// ---------------------------------------------------------------------------
// Stage 0: split fp32 -> bf16 hi/lo  (2 float4 per thread for ILP)
// ---------------------------------------------------------------------------
__global__ __launch_bounds__(256) void conv_split(const float* __restrict__ in,
                                                  int which, int kind, int n4)
{
    __nv_bfloat16* hi = kind ? g_wh[which] : g_xh[which];
    __nv_bfloat16* lo = kind ? g_wl[which] : g_xl[which];
    int i0 = blockIdx.x * 512 + threadIdx.x;
#pragma unroll
    for (int u = 0; u < 2; u++) {
        int idx = i0 + u * 256;
        if (idx < n4) {
            float4 v = ((const float4*)in)[idx];
            uint32_t h0, l0, h1, l1;
            split_pack(v.x, v.y, h0, l0);
            split_pack(v.z, v.w, h1, l1);
            ((uint2*)hi)[idx] = make_uint2(h0, h1);
            ((uint2*)lo)[idx] = make_uint2(l0, l1);
        }
    }
}

// ---------------------------------------------------------------------------
// Stage 1: projection GEMM, cp.async double-buffered, K-tile 32
// CTA: 128 rows x 2 heads (N=128). grid (H/2, M/128, 3)
// ---------------------------------------------------------------------------
#define PX2 80    // X pitch: 32 halves + pad
#define PW  272   // W pitch: 128 halves + pad

static constexpr int PSXH = 0;
static constexpr int PSXL = PSXH + 128 * PX2;   // 10240
static constexpr int PSWH = PSXL + 128 * PX2;   // 20480
static constexpr int PSWL = PSWH + 32 * PW;     // 29184
static constexpr int PSTG = PSWL + 32 * PW;     // 37888 per stage
static constexpr int PROJ_SMEM = 2 * PSTG;      // 75776

__device__ __forceinline__ void proj_issue(
    uint32_t sbase, const __nv_bfloat16* Xh, const __nv_bfloat16* Xl,
    const __nv_bfloat16* Wh_, const __nv_bfloat16* Wl_,
    int m0, int h0, int k0, int t)
{
#pragma unroll
    for (int j = 0; j < 2; j++) {
        int idx = t + 256 * j;
        int r = idx >> 2, c8 = (idx & 3) * 8;
        size_t go = (size_t)(m0 + r) * DD + k0 + c8;
        uint32_t so = sbase + r * PX2 + c8 * 2;
        cpa16(so + PSXH, Xh + go);
        cpa16(so + PSXL, Xl + go);
    }
#pragma unroll
    for (int j = 0; j < 2; j++) {
        int idx = t + 256 * j;
        int r = idx >> 4, c8 = (idx & 15) * 8;
        int hh_ = h0 + (c8 >> 6), a = c8 & 63;
        size_t go = ((size_t)hh_ * DD + (k0 + r)) * AA + a;
        uint32_t so = sbase + r * PW + c8 * 2;
        cpa16(so + PSWH, Wh_ + go);
        cpa16(so + PSWL, Wl_ + go);
    }
}

__global__ __launch_bounds__(256, 2) void proj_mma(
    const float* __restrict__ bq, const float* __restrict__ bk,
    const float* __restrict__ bv)
{
    extern __shared__ char smc[];
    const uint32_t sb = smem_u32(smc);
    const int t = threadIdx.x, lane = t & 31, w = t >> 5;
    const int h0 = blockIdx.x * 2;
    const int m0 = blockIdx.y * 128;
    const int which = blockIdx.z;
    const float* bias = (which == 0) ? bq : (which == 1) ? bk : bv;

    const __nv_bfloat16* Xh = g_xh[which];
    const __nv_bfloat16* Xl = g_xl[which];
    const __nv_bfloat16* Wh_ = g_wh[which];
    const __nv_bfloat16* Wl_ = g_wl[which];
    __nv_bfloat16* Oh = g_ph[which];
    __nv_bfloat16* Ol = g_pl[which];

    const int lr  = lane & 7;
    const int grp = lane >> 3;
    const uint32_t a_row = 16 * w + lr + (grp & 1) * 8;
    const uint32_t a_cb  = (grp >> 1) * 16;
    const uint32_t wb_row = lr + (grp & 1) * 8;
    const uint32_t wb_cb  = (grp >> 1) * 16;

    float acc[16][4];
#pragma unroll
    for (int i = 0; i < 16; i++)
#pragma unroll
        for (int j = 0; j < 4; j++) acc[i][j] = 0.f;

    // prologue
    proj_issue(sb, Xh, Xl, Wh_, Wl_, m0, h0, 0, t);
    CP_COMMIT();

    const int NIT = DD / 32;  // 32
    for (int it = 0; it < NIT; it++) {
        __syncthreads();
        if (it + 1 < NIT) {
            proj_issue(sb + ((it + 1) & 1) * PSTG, Xh, Xl, Wh_, Wl_, m0, h0, (it + 1) * 32, t);
            CP_COMMIT();
            CP_WAIT(1);
        } else {
            CP_WAIT(0);
        }
        __syncthreads();

        const uint32_t st = sb + (it & 1) * PSTG;
        const uint32_t axh = st + PSXH + a_row * PX2 + a_cb;
        const uint32_t axl = st + PSXL + a_row * PX2 + a_cb;
#pragma unroll
        for (int ks = 0; ks < 2; ks++) {
            uint32_t xh0, xh1, xh2, xh3, xl0, xl1, xl2, xl3;
            ldsm4(xh0, xh1, xh2, xh3, axh + ks * 32);
            ldsm4(xl0, xl1, xl2, xl3, axl + ks * 32);
#pragma unroll
            for (int np = 0; np < 8; np++) {
                uint32_t wh0, wh1, wh2, wh3, wl0, wl1, wl2, wl3;
                uint32_t waddr = st + (ks * 16 + wb_row) * PW + np * 32 + wb_cb;
                ldsm4t(wh0, wh1, wh2, wh3, PSWH + waddr);
                ldsm4t(wl0, wl1, wl2, wl3, PSWL + waddr);
                mma16816(acc[2*np],   xh0, xh1, xh2, xh3, wh0, wh1);
                mma16816(acc[2*np+1], xh0, xh1, xh2, xh3, wh2, wh3);
                mma16816(acc[2*np],   xh0, xh1, xh2, xh3, wl0, wl1);
                mma16816(acc[2*np+1], xh0, xh1, xh2, xh3, wl2, wl3);
                mma16816(acc[2*np],   xl0, xl1, xl2, xl3, wh0, wh1);
                mma16816(acc[2*np+1], xl0, xl1, xl2, xl3, wh2, wh3);
            }
        }
    }

    // epilogue
    const int bidx = m0 / SS;
    const int srow = m0 % SS;
    const int rlo = lane >> 2;
    const int cp  = 2 * (lane & 3);
#pragma unroll
    for (int j = 0; j < 16; j++) {
        int n = 8 * j + cp;
        int hh_ = h0 + (n >> 6);
        int a = n & 63;
        float b0 = bias[hh_ * AA + a], b1 = bias[hh_ * AA + a + 1];
        int s0 = srow + 16 * w + rlo;
        size_t o0 = ((size_t)(bidx * HH + hh_) * SS + s0) * AA + a;
        size_t o1 = o0 + (size_t)8 * AA;
        uint32_t hv, lv;
        split_pack(acc[j][0] + b0, acc[j][1] + b1, hv, lv);
        *(uint32_t*)(Oh + o0) = hv; *(uint32_t*)(Ol + o0) = lv;
        split_pack(acc[j][2] + b0, acc[j][3] + b1, hv, lv);
        *(uint32_t*)(Oh + o1) = hv; *(uint32_t*)(Ol + o1) = lv;
    }
}

// ---------------------------------------------------------------------------
// Stage 2: flash attention, cp.async double-buffered K/V chunks of 64
// ---------------------------------------------------------------------------
#define PITCH 144

static constexpr int AKH = 0;
static constexpr int AKL = AKH + 64 * PITCH;    // 9216
static constexpr int AVH = AKL + 64 * PITCH;    // 18432
static constexpr int AVL = AVH + 64 * PITCH;    // 27648
static constexpr int ASTG = AVL + 64 * PITCH;   // 36864 per stage
static constexpr int ASQH = 2 * ASTG;           // 73728
static constexpr int ASQL = ASQH + 128 * PITCH; // 92160
static constexpr int ATTN_SMEM = ASQL + 128 * PITCH; // 110592

__device__ __forceinline__ void attn_issue(
    uint32_t sbase, const __nv_bfloat16* kh, const __nv_bfloat16* kl,
    const __nv_bfloat16* vh, const __nv_bfloat16* vl, int t)
{
#pragma unroll
    for (int j = 0; j < 2; j++) {
        int idx = t + 256 * j;
        int r = idx >> 3, c8 = (idx & 7) * 8;
        size_t go = (size_t)r * AA + c8;
        uint32_t so = sbase + r * PITCH + c8 * 2;
        cpa16(so + AKH, kh + go);
        cpa16(so + AKL, kl + go);
        cpa16(so + AVH, vh + go);
        cpa16(so + AVL, vl + go);
    }
}

__global__ __launch_bounds__(256, 2) void attn_mma(float* __restrict__ out)
{
    extern __shared__ char smc[];
    const uint32_t sb = smem_u32(smc);
    const int t = threadIdx.x, lane = t & 31, w = t >> 5;
    const int qt = blockIdx.x, h = blockIdx.y, b = blockIdx.z;
    const size_t bh = (size_t)(b * HH + h) * SS;

    const __nv_bfloat16* kh0 = g_ph[1] + bh * AA;
    const __nv_bfloat16* kl0 = g_pl[1] + bh * AA;
    const __nv_bfloat16* vh0 = g_ph[2] + bh * AA;
    const __nv_bfloat16* vl0 = g_pl[2] + bh * AA;

    // prologue: issue chunk 0
    attn_issue(sb, kh0, kl0, vh0, vl0, t);
    CP_COMMIT();

    // load Q (regular stores, separate region)
    {
        const __nv_bfloat16* qh = g_ph[0] + (bh + qt * 128) * AA;
        const __nv_bfloat16* ql = g_pl[0] + (bh + qt * 128) * AA;
#pragma unroll
        for (int j = 0; j < 4; j++) {
            int idx = t + 256 * j;
            int r = idx >> 3, c = (idx & 7) * 8;
            *(uint4*)(smc + ASQH + r * PITCH + c * 2) = *(const uint4*)(qh + (size_t)r * AA + c);
            *(uint4*)(smc + ASQL + r * PITCH + c * 2) = *(const uint4*)(ql + (size_t)r * AA + c);
        }
    }

    const int lr  = lane & 7;
    const int grp = lane >> 3;
    const uint32_t a_row = 16 * w + lr + (grp & 1) * 8;
    const uint32_t a_cb  = (grp >> 1) * 16;
    const uint32_t kb_row = lr + (grp >> 1) * 8;
    const uint32_t kb_cb  = (grp & 1) * 16;
    const uint32_t vb_row = lr + (grp & 1) * 8;
    const uint32_t vb_cb  = (grp >> 1) * 16;

    const uint32_t aqh = sb + ASQH + a_row * PITCH + a_cb;
    const uint32_t aql = sb + ASQL + a_row * PITCH + a_cb;

    float oacc[8][4];
#pragma unroll
    for (int i = 0; i < 8; i++)
#pragma unroll
        for (int j = 0; j < 4; j++) oacc[i][j] = 0.f;
    float lA = 0.f, lB = 0.f, CA = 0.f, CB = 0.f;

    const int NIT = SS / 64;  // 32
    for (int kt = 0; kt < NIT; kt++) {
        __syncthreads();
        if (kt + 1 < NIT) {
            size_t ko = (size_t)(kt + 1) * 64 * AA;
            attn_issue(sb + ((kt + 1) & 1) * ASTG, kh0 + ko, kl0 + ko, vh0 + ko, vl0 + ko, t);
            CP_COMMIT();
            CP_WAIT(1);
        } else {
            CP_WAIT(0);
        }
        __syncthreads();

        const uint32_t st = sb + (kt & 1) * ASTG;

        float sacc[8][4];
#pragma unroll
        for (int i = 0; i < 8; i++)
#pragma unroll
            for (int j = 0; j < 4; j++) sacc[i][j] = 0.f;

#pragma unroll
        for (int ks = 0; ks < 4; ks++) {
            uint32_t qh0, qh1, qh2, qh3, ql0, ql1, ql2, ql3;
            ldsm4(qh0, qh1, qh2, qh3, aqh + ks * 32);
            ldsm4(ql0, ql1, ql2, ql3, aql + ks * 32);
#pragma unroll
            for (int np = 0; np < 4; np++) {
                uint32_t kh0r, kh1r, kh2r, kh3r, kl0r, kl1r, kl2r, kl3r;
                uint32_t kaddr = st + (np * 16 + kb_row) * PITCH + ks * 32 + kb_cb;
                ldsm4(kh0r, kh1r, kh2r, kh3r, AKH + kaddr);
                ldsm4(kl0r, kl1r, kl2r, kl3r, AKL + kaddr);
                mma16816(sacc[2*np],   qh0, qh1, qh2, qh3, kh0r, kh1r);
                mma16816(sacc[2*np+1], qh0, qh1, qh2, qh3, kh2r, kh3r);
                mma16816(sacc[2*np],   qh0, qh1, qh2, qh3, kl0r, kl1r);
                mma16816(sacc[2*np+1], qh0, qh1, qh2, qh3, kl2r, kl3r);
                mma16816(sacc[2*np],   ql0, ql1, ql2, ql3, kh0r, kh1r);
                mma16816(sacc[2*np+1], ql0, ql1, ql2, ql3, kh2r, kh3r);
            }
        }

        if (kt == 0) {
            float mA = -1e30f, mB = -1e30f;
#pragma unroll
            for (int i = 0; i < 8; i++) {
                mA = fmaxf(mA, fmaxf(sacc[i][0], sacc[i][1]));
                mB = fmaxf(mB, fmaxf(sacc[i][2], sacc[i][3]));
            }
            mA = fmaxf(mA, __shfl_xor_sync(0xffffffffu, mA, 1));
            mA = fmaxf(mA, __shfl_xor_sync(0xffffffffu, mA, 2));
            mB = fmaxf(mB, __shfl_xor_sync(0xffffffffu, mB, 1));
            mB = fmaxf(mB, __shfl_xor_sync(0xffffffffu, mB, 2));
            CA = mA; CB = mB;
        }
#pragma unroll
        for (int i = 0; i < 8; i++) {
            sacc[i][0] = __expf(sacc[i][0] - CA);
            sacc[i][1] = __expf(sacc[i][1] - CA);
            sacc[i][2] = __expf(sacc[i][2] - CB);
            sacc[i][3] = __expf(sacc[i][3] - CB);
            lA += sacc[i][0] + sacc[i][1];
            lB += sacc[i][2] + sacc[i][3];
        }

#pragma unroll
        for (int ks = 0; ks < 4; ks++) {
            uint32_t ph0, ph1, ph2, ph3, pl0, pl1, pl2, pl3;
            split_pack(sacc[2*ks][0],   sacc[2*ks][1],   ph0, pl0);
            split_pack(sacc[2*ks][2],   sacc[2*ks][3],   ph1, pl1);
            split_pack(sacc[2*ks+1][0], sacc[2*ks+1][1], ph2, pl2);
            split_pack(sacc[2*ks+1][2], sacc[2*ks+1][3], ph3, pl3);
#pragma unroll
            for (int np = 0; np < 4; np++) {
                uint32_t vh0r, vh1r, vh2r, vh3r, vl0r, vl1r, vl2r, vl3r;
                uint32_t vaddr = st + (ks * 16 + vb_row) * PITCH + np * 32 + vb_cb;
                ldsm4t(vh0r, vh1r, vh2r, vh3r, AVH + vaddr);
                ldsm4t(vl0r, vl1r, vl2r, vl3r, AVL + vaddr);
                mma16816(oacc[2*np],   ph0, ph1, ph2, ph3, vh0r, vh1r);
                mma16816(oacc[2*np+1], ph0, ph1, ph2, ph3, vh2r, vh3r);
                mma16816(oacc[2*np],   ph0, ph1, ph2, ph3, vl0r, vl1r);
                mma16816(oacc[2*np+1], ph0, ph1, ph2, ph3, vl2r, vl3r);
                mma16816(oacc[2*np],   pl0, pl1, pl2, pl3, vh0r, vh1r);
                mma16816(oacc[2*np+1], pl0, pl1, pl2, pl3, vh2r, vh3r);
            }
        }
    }

    lA += __shfl_xor_sync(0xffffffffu, lA, 1);
    lA += __shfl_xor_sync(0xffffffffu, lA, 2);
    lB += __shfl_xor_sync(0xffffffffu, lB, 1);
    lB += __shfl_xor_sync(0xffffffffu, lB, 2);
    float invA = 1.f / lA, invB = 1.f / lB;

    int rA = qt * 128 + 16 * w + (lane >> 2);
    int col = 2 * (lane & 3);
    float* oA = out + ((size_t)(b * SS + rA)) * (HH * AA) + h * AA + col;
    float* oB = oA + 8 * (HH * AA);
#pragma unroll
    for (int j = 0; j < 8; j++) {
        float2 vA = make_float2(oacc[j][0] * invA, oacc[j][1] * invA);
        float2 vB = make_float2(oacc[j][2] * invB, oacc[j][3] * invB);
        *(float2*)(oA + j * 8) = vA;
        *(float2*)(oB + j * 8) = vB;
    }
}

// ---------------------------------------------------------------------------

extern "C" void kernel_launch(void* const* d_in, const int* in_sizes, int n_in,
                              void* d_out, int out_size)
{
    const float* q  = (const float*)d_in[0];
    const float* k  = (const float*)d_in[1];
    const float* v  = (const float*)d_in[2];
    const float* Wq = (const float*)d_in[3];
    const float* bq = (const float*)d_in[4];
    const float* Wk = (const float*)d_in[5];
    const float* bk = (const float*)d_in[6];
    const float* Wv = (const float*)d_in[7];
    const float* bv = (const float*)d_in[8];
    float* out = (float*)d_out;

    cudaFuncSetAttribute(proj_mma, cudaFuncAttributeMaxDynamicSharedMemorySize, PROJ_SMEM);
    cudaFuncSetAttribute(attn_mma, cudaFuncAttributeMaxDynamicSharedMemorySize, ATTN_SMEM);

    conv_split<<<NX/4/512, 256>>>(q, 0, 0, NX/4);
    conv_split<<<NX/4/512, 256>>>(k, 1, 0, NX/4);
    conv_split<<<NX/4/512, 256>>>(v, 2, 0, NX/4);
    conv_split<<<NW/4/512, 256>>>(Wq, 0, 1, NW/4);
    conv_split<<<NW/4/512, 256>>>(Wk, 1, 1, NW/4);
    conv_split<<<NW/4/512, 256>>>(Wv, 2, 1, NW/4);

    dim3 pgrid(HH/2, 64, 3);
    proj_mma<<<pgrid, 256, PROJ_SMEM>>>(bq, bk, bv);

    dim3 agrid(16, 16, 4);
    attn_mma<<<agrid, 256, ATTN_SMEM>>>(out);
}